// round 11
// baseline (speedup 1.0000x reference)
#include <cuda_runtime.h>
#include <cuda_bf16.h>
#include <cuda_fp16.h>
#include <math.h>

// ---------------------------------------------------------------------------
// EncoderLayer: x[1,4096,512] -> full transformer encoder layer.
//   fp16 (m16n8k16) tensor-core GEMMs (BM=128 everywhere; BM=64 measured
//   slower: tensor util 21.5%) + bf16 flash attention (BKV=64, exp2 softmax).
// ---------------------------------------------------------------------------

#define S_LEN 4096
#define DM    512
#define DFF_  2048
#define NH    8
#define DH    64

// Scratch (device globals: no allocation allowed in kernel_launch)
__device__ __half g_xh [S_LEN * DM];
__device__ __half g_wqh[DM * DM];
__device__ __half g_wkh[DM * DM];
__device__ __half g_wvh[DM * DM];
__device__ __half g_dwh[DM * DM];
__device__ __half g_l1h[DFF_ * DM];
__device__ __half g_l2h[DM * DFF_];
__device__ __nv_bfloat16 g_Qb[S_LEN * DM];
__device__ __nv_bfloat16 g_Kb[S_LEN * DM];
__device__ __nv_bfloat16 g_Vb[S_LEN * DM];
__device__ __half g_CTXh[S_LEN * DM];
__device__ __half g_O1h [S_LEN * DM];
__device__ __half g_Hh  [S_LEN * DFF_];
__device__ float g_ATT[S_LEN * DM];
__device__ float g_O1 [S_LEN * DM];
__device__ float g_F  [S_LEN * DM];

// ---------------------------------------------------------------------------
// PTX helpers
// ---------------------------------------------------------------------------
__device__ __forceinline__ void mma_bf16(float* c, const unsigned* a,
                                         unsigned b0, unsigned b1) {
    asm volatile(
        "mma.sync.aligned.m16n8k16.row.col.f32.bf16.bf16.f32 "
        "{%0,%1,%2,%3}, {%4,%5,%6,%7}, {%8,%9}, {%0,%1,%2,%3};"
        : "+f"(c[0]), "+f"(c[1]), "+f"(c[2]), "+f"(c[3])
        : "r"(a[0]), "r"(a[1]), "r"(a[2]), "r"(a[3]), "r"(b0), "r"(b1));
}

__device__ __forceinline__ void mma_f16(float* c, const unsigned* a,
                                        unsigned b0, unsigned b1) {
    asm volatile(
        "mma.sync.aligned.m16n8k16.row.col.f32.f16.f16.f32 "
        "{%0,%1,%2,%3}, {%4,%5,%6,%7}, {%8,%9}, {%0,%1,%2,%3};"
        : "+f"(c[0]), "+f"(c[1]), "+f"(c[2]), "+f"(c[3])
        : "r"(a[0]), "r"(a[1]), "r"(a[2]), "r"(a[3]), "r"(b0), "r"(b1));
}

__device__ __forceinline__ void ldsm_x4(unsigned& d0, unsigned& d1,
                                        unsigned& d2, unsigned& d3, unsigned addr) {
    asm volatile("ldmatrix.sync.aligned.m8n8.x4.shared.b16 {%0,%1,%2,%3}, [%4];"
                 : "=r"(d0), "=r"(d1), "=r"(d2), "=r"(d3) : "r"(addr));
}

__device__ __forceinline__ void ldsm_x4_t(unsigned& d0, unsigned& d1,
                                          unsigned& d2, unsigned& d3, unsigned addr) {
    asm volatile("ldmatrix.sync.aligned.m8n8.x4.trans.shared.b16 {%0,%1,%2,%3}, [%4];"
                 : "=r"(d0), "=r"(d1), "=r"(d2), "=r"(d3) : "r"(addr));
}

__device__ __forceinline__ unsigned pack_bf16(float lo, float hi) {
    unsigned r;
    asm("cvt.rn.bf16x2.f32 %0, %1, %2;" : "=r"(r) : "f"(hi), "f"(lo));
    return r;
}

__device__ __forceinline__ unsigned pack_f16(float lo, float hi) {
    unsigned r;
    asm("{\n\t.reg .f16 l, h;\n\tcvt.rn.f16.f32 l, %1;\n\tcvt.rn.f16.f32 h, %2;\n\t"
        "mov.b32 %0, {l, h};\n\t}" : "=r"(r) : "f"(lo), "f"(hi));
    return r;
}

__device__ __forceinline__ float ex2(float x) {
    float r;
    asm("ex2.approx.f32 %0, %1;" : "=f"(r) : "f"(x));
    return r;
}

__device__ __forceinline__ void cp16(unsigned dst, const void* src) {
    asm volatile("cp.async.cg.shared.global [%0], [%1], 16;"
                 :: "r"(dst), "l"(src));
}

// ---------------------------------------------------------------------------
// Merged f32 -> f16 convert: all 7 tensors in ONE launch (5120 blocks).
// ---------------------------------------------------------------------------
__global__ void __launch_bounds__(256)
f2h_all_kernel(const float* __restrict__ x,  __half* __restrict__ xh,
               const float* __restrict__ wq, __half* __restrict__ wqh,
               const float* __restrict__ wk, __half* __restrict__ wkh,
               const float* __restrict__ wv, __half* __restrict__ wvh,
               const float* __restrict__ dw, __half* __restrict__ dwh,
               const float* __restrict__ l1, __half* __restrict__ l1h,
               const float* __restrict__ l2, __half* __restrict__ l2h)
{
    int b = blockIdx.x;
    const float* src; __half* dst; int lb;
    if      (b < 2048) { src = x;  dst = xh;  lb = b; }
    else if (b < 2304) { src = wq; dst = wqh; lb = b - 2048; }
    else if (b < 2560) { src = wk; dst = wkh; lb = b - 2304; }
    else if (b < 2816) { src = wv; dst = wvh; lb = b - 2560; }
    else if (b < 3072) { src = dw; dst = dwh; lb = b - 2816; }
    else if (b < 4096) { src = l1; dst = l1h; lb = b - 3072; }
    else               { src = l2; dst = l2h; lb = b - 4096; }
    int i = (lb * 256 + threadIdx.x) * 4;
    float4 v = *(const float4*)(src + i);
    *(uint2*)(dst + i) = make_uint2(pack_f16(v.x, v.y), pack_f16(v.z, v.w));
}

// ---------------------------------------------------------------------------
// fp16 tensor-core NT GEMM: C[M,N] = (A[M,K] * W[N,K]^T + bias) * scale (+ReLU)
// Block tile 128x128, BK=32 fp16, 256 threads (8 warps: 2 row-halves x
// 4 col-quarters), double-buffered cp.async, ldmatrix fragments.
// OUT: 0 = fp32, 1 = bf16, 2 = fp16.
// blockIdx.z selects among up to 3 weight/bias/output sets (batched QKV).
// ---------------------------------------------------------------------------
#define HSTR 40
#define HTILE (128 * HSTR)   // fp16 units per tile

template<bool RELU, int OUT>
__global__ void __launch_bounds__(256)
gemm_f16_kernel(const __half* __restrict__ A,
                const __half* __restrict__ W0, const float* __restrict__ bi0, void* __restrict__ C0,
                const __half* __restrict__ W1, const float* __restrict__ bi1, void* __restrict__ C1,
                const __half* __restrict__ W2, const float* __restrict__ bi2, void* __restrict__ C2,
                int N, int K, float s0, float s1, float s2)
{
    __shared__ __half As[2][HTILE];   // 20480 B
    __shared__ __half Bs[2][HTILE];   // 20480 B

    const __half* B    = W0;
    const float*  bias = bi0;
    void*         Cv   = C0;
    float         scl  = s0;
    if (blockIdx.z == 1) { B = W1; bias = bi1; Cv = C1; scl = s1; }
    if (blockIdx.z == 2) { B = W2; bias = bi2; Cv = C2; scl = s2; }

    const int t    = threadIdx.x;
    const int w    = t >> 5;
    const int lane = t & 31;
    const int grp  = lane >> 2;
    const int tig  = lane & 3;
    const int wm   = w >> 2;      // 0..1 : 64-row half
    const int wn   = w & 3;       // 0..3 : 32-col quarter
    const int m0   = blockIdx.y * 128;
    const int n0   = blockIdx.x * 128;
    const int NC   = K >> 5;      // K-chunks of 32

    // loader: thread t -> row t>>1, two 16B chunks (8 fp16 each)
    const int lrow = t >> 1;
    const int lc   = (t & 1) * 2;

    const unsigned aB = (unsigned)__cvta_generic_to_shared(&As[0][0]);
    const unsigned bB = (unsigned)__cvta_generic_to_shared(&Bs[0][0]);

    float acc[4][4][4];
    #pragma unroll
    for (int i = 0; i < 4; ++i)
        #pragma unroll
        for (int j = 0; j < 4; ++j)
            #pragma unroll
            for (int c = 0; c < 4; ++c) acc[i][j][c] = 0.f;

    #define HGLOAD(KT, BUF)                                                     \
        {                                                                       \
            const __half* a = A + (size_t)(m0 + lrow) * K + (KT) + lc * 8;      \
            const __half* b = B + (size_t)(n0 + lrow) * K + (KT) + lc * 8;      \
            const unsigned ad = aB + (unsigned)(((BUF)*HTILE + lrow*HSTR + lc*8) * 2); \
            const unsigned bd = bB + (unsigned)(((BUF)*HTILE + lrow*HSTR + lc*8) * 2); \
            cp16(ad,       a);                                                  \
            cp16(ad + 16u, a + 8);                                              \
            cp16(bd,       b);                                                  \
            cp16(bd + 16u, b + 8);                                              \
        }

    HGLOAD(0, 0);
    asm volatile("cp.async.commit_group;" ::: "memory");

    for (int it = 0; it < NC; ++it) {
        const int buf = it & 1;
        if (it + 1 < NC) {
            HGLOAD((it + 1) << 5, buf ^ 1);
            asm volatile("cp.async.commit_group;" ::: "memory");
            asm volatile("cp.async.wait_group 1;" ::: "memory");
        } else {
            asm volatile("cp.async.wait_group 0;" ::: "memory");
        }
        __syncthreads();

        const unsigned aS = aB + (unsigned)(buf * HTILE * 2);
        const unsigned bS = bB + (unsigned)(buf * HTILE * 2);

        // B fragments: 4 n8-tiles, each one ldsm.x4 covering all 32 k
        unsigned bf[4][4];
        #pragma unroll
        for (int j = 0; j < 4; ++j)
            ldsm_x4(bf[j][0], bf[j][1], bf[j][2], bf[j][3],
                    bS + (unsigned)(((wn*32 + j*8 + (lane & 7)) * HSTR
                                     + (lane >> 3) * 8) * 2));

        // two k16 chunks
        #pragma unroll
        for (int kc = 0; kc < 2; ++kc) {
            unsigned af[4][4];
            #pragma unroll
            for (int i = 0; i < 4; ++i)
                ldsm_x4(af[i][0], af[i][1], af[i][2], af[i][3],
                        aS + (unsigned)(((wm*64 + i*16 + (lane & 15)) * HSTR
                                         + kc*16 + (lane >> 4) * 8) * 2));
            #pragma unroll
            for (int i = 0; i < 4; ++i)
                #pragma unroll
                for (int j = 0; j < 4; ++j)
                    mma_f16(acc[i][j], af[i], bf[j][2*kc], bf[j][2*kc + 1]);
        }
        __syncthreads();
    }
    #undef HGLOAD

    // epilogue: (acc + bias) * scale (+relu)
    #pragma unroll
    for (int j = 0; j < 4; ++j) {
        const int col = n0 + wn*32 + j*8 + 2*tig;
        const float2 bj = *(const float2*)&bias[col];
        #pragma unroll
        for (int i = 0; i < 4; ++i) {
            const int row = m0 + wm*64 + i*16 + grp;
            float2 v0 = make_float2((acc[i][j][0] + bj.x) * scl, (acc[i][j][1] + bj.y) * scl);
            float2 v1 = make_float2((acc[i][j][2] + bj.x) * scl, (acc[i][j][3] + bj.y) * scl);
            if (RELU) {
                v0.x = fmaxf(v0.x, 0.f); v0.y = fmaxf(v0.y, 0.f);
                v1.x = fmaxf(v1.x, 0.f); v1.y = fmaxf(v1.y, 0.f);
            }
            if (OUT == 1) {
                __nv_bfloat16* Cb = (__nv_bfloat16*)Cv;
                *(unsigned*)&Cb[(size_t)row       * N + col] = pack_bf16(v0.x, v0.y);
                *(unsigned*)&Cb[(size_t)(row + 8) * N + col] = pack_bf16(v1.x, v1.y);
            } else if (OUT == 2) {
                __half* Ch = (__half*)Cv;
                *(unsigned*)&Ch[(size_t)row       * N + col] = pack_f16(v0.x, v0.y);
                *(unsigned*)&Ch[(size_t)(row + 8) * N + col] = pack_f16(v1.x, v1.y);
            } else {
                float* Cf = (float*)Cv;
                *(float2*)&Cf[(size_t)row       * N + col] = v0;
                *(float2*)&Cf[(size_t)(row + 8) * N + col] = v1;
            }
        }
    }
}

// ---------------------------------------------------------------------------
// bf16 tensor-core flash attention, BKV=64, exp2-domain softmax.
// CTA = (head, 64-query block), 128 threads = 4 warps x 16 query rows.
// Q pre-scaled by (1/sqrt(DH)) * log2(e) at the QKV epilogue.
// ---------------------------------------------------------------------------
#define BKV   64
#define NTT   (S_LEN / BKV)   // 64
#define KSTRb 72              // bf16 units; 144B row stride (9 x 16B)
#define PSTRb 72

__global__ void __launch_bounds__(128)
flash_attn_bf16_kernel(const __nv_bfloat16* __restrict__ Q,
                       const __nv_bfloat16* __restrict__ K,
                       const __nv_bfloat16* __restrict__ V,
                       __half* __restrict__ O)
{
    __shared__ __nv_bfloat16 Ks[2][BKV * KSTRb];   // 18432 B
    __shared__ __nv_bfloat16 Vs[2][BKV * KSTRb];   // 18432 B
    __shared__ __nv_bfloat16 Ps[64 * PSTRb];       //  9216 B

    const int t    = threadIdx.x;
    const int w    = t >> 5;
    const int lane = t & 31;
    const int grp  = lane >> 2;
    const int tig  = lane & 3;
    const int h    = blockIdx.y;
    const int q0   = blockIdx.x * 64;

    unsigned qa[4][4];
    {
        const __nv_bfloat16* Qb = Q + (size_t)(q0 + w * 16) * DM + h * DH;
        #pragma unroll
        for (int kc = 0; kc < 4; ++kc) {
            qa[kc][0] = *(const unsigned*)&Qb[(size_t)grp       * DM + kc*16 + 2*tig];
            qa[kc][1] = *(const unsigned*)&Qb[(size_t)(grp + 8) * DM + kc*16 + 2*tig];
            qa[kc][2] = *(const unsigned*)&Qb[(size_t)grp       * DM + kc*16 + 8 + 2*tig];
            qa[kc][3] = *(const unsigned*)&Qb[(size_t)(grp + 8) * DM + kc*16 + 8 + 2*tig];
        }
    }

    float of[8][4];
    #pragma unroll
    for (int n = 0; n < 8; ++n)
        #pragma unroll
        for (int c = 0; c < 4; ++c) of[n][c] = 0.f;

    float m0 = -1e30f, m1 = -1e30f, l0 = 0.f, l1 = 0.f;

    const unsigned ksBase = (unsigned)__cvta_generic_to_shared(&Ks[0][0]);
    const unsigned vsBase = (unsigned)__cvta_generic_to_shared(&Vs[0][0]);

    const int lr = t >> 3;
    const int c8 = t & 7;

    #define LOAD_TILE(KB, B)                                                          \
        {                                                                             \
            const size_t krow = (size_t)((KB) * BKV);                                 \
            _Pragma("unroll")                                                         \
            for (int i = 0; i < 4; ++i) {                                             \
                const int r = lr + 16 * i;                                            \
                cp16(ksBase + (unsigned)((((B)*BKV + r)*KSTRb + c8*8) * 2),           \
                     K + (krow + r) * DM + h * DH + c8 * 8);                          \
                cp16(vsBase + (unsigned)((((B)*BKV + r)*KSTRb + c8*8) * 2),           \
                     V + (krow + r) * DM + h * DH + c8 * 8);                          \
            }                                                                         \
        }

    LOAD_TILE(0, 0);
    asm volatile("cp.async.commit_group;" ::: "memory");

    for (int kb = 0; kb < NTT; ++kb) {
        const int buf = kb & 1;
        if (kb + 1 < NTT) {
            LOAD_TILE(kb + 1, buf ^ 1);
            asm volatile("cp.async.commit_group;" ::: "memory");
            asm volatile("cp.async.wait_group 1;" ::: "memory");
        } else {
            asm volatile("cp.async.wait_group 0;" ::: "memory");
        }
        __syncthreads();

        const unsigned kbuf = ksBase + (unsigned)(buf * BKV * KSTRb * 2);
        const unsigned vbuf = vsBase + (unsigned)(buf * BKV * KSTRb * 2);

        // ---- S = Qs K^T : 16x64 per warp ----
        float sf[8][4];
        #pragma unroll
        for (int n = 0; n < 8; ++n) {
            sf[n][0] = sf[n][1] = sf[n][2] = sf[n][3] = 0.f;
            #pragma unroll
            for (int kcp = 0; kcp < 2; ++kcp) {
                unsigned d0, d1, d2, d3;
                const unsigned addr = kbuf +
                    (unsigned)(((n*8 + (lane & 7)) * KSTRb + kcp*32 + (lane >> 3) * 8) * 2);
                ldsm_x4(d0, d1, d2, d3, addr);
                mma_bf16(sf[n], qa[2*kcp],     d0, d1);
                mma_bf16(sf[n], qa[2*kcp + 1], d2, d3);
            }
        }

        // ---- online softmax in log2 domain (rows grp / grp+8) ----
        float mx0 = -1e30f, mx1 = -1e30f;
        #pragma unroll
        for (int n = 0; n < 8; ++n) {
            mx0 = fmaxf(mx0, fmaxf(sf[n][0], sf[n][1]));
            mx1 = fmaxf(mx1, fmaxf(sf[n][2], sf[n][3]));
        }
        mx0 = fmaxf(mx0, __shfl_xor_sync(0xffffffffu, mx0, 1));
        mx0 = fmaxf(mx0, __shfl_xor_sync(0xffffffffu, mx0, 2));
        mx1 = fmaxf(mx1, __shfl_xor_sync(0xffffffffu, mx1, 1));
        mx1 = fmaxf(mx1, __shfl_xor_sync(0xffffffffu, mx1, 2));

        const float mn0 = fmaxf(m0, mx0);
        const float mn1 = fmaxf(m1, mx1);
        const float al0 = ex2(m0 - mn0);
        const float al1 = ex2(m1 - mn1);

        float s0 = 0.f, s1 = 0.f;
        #pragma unroll
        for (int n = 0; n < 8; ++n) {
            sf[n][0] = ex2(sf[n][0] - mn0); s0 += sf[n][0];
            sf[n][1] = ex2(sf[n][1] - mn0); s0 += sf[n][1];
            sf[n][2] = ex2(sf[n][2] - mn1); s1 += sf[n][2];
            sf[n][3] = ex2(sf[n][3] - mn1); s1 += sf[n][3];
        }
        s0 += __shfl_xor_sync(0xffffffffu, s0, 1);
        s0 += __shfl_xor_sync(0xffffffffu, s0, 2);
        s1 += __shfl_xor_sync(0xffffffffu, s1, 1);
        s1 += __shfl_xor_sync(0xffffffffu, s1, 2);

        l0 = l0 * al0 + s0;  m0 = mn0;
        l1 = l1 * al1 + s1;  m1 = mn1;

        #pragma unroll
        for (int n = 0; n < 8; ++n) {
            of[n][0] *= al0; of[n][1] *= al0;
            of[n][2] *= al1; of[n][3] *= al1;
        }

        // ---- store P (64 cols) to per-warp-private bf16 smem rows ----
        {
            __nv_bfloat16* pr = &Ps[(w*16 + grp) * PSTRb];
            #pragma unroll
            for (int n = 0; n < 8; ++n) {
                *(unsigned*)&pr[n*8 + 2*tig]           = pack_bf16(sf[n][0], sf[n][1]);
                *(unsigned*)&pr[8*PSTRb + n*8 + 2*tig] = pack_bf16(sf[n][2], sf[n][3]);
            }
        }
        __syncwarp();

        // ---- P A-fragments (4 k16 chunks over 64 keys) ----
        unsigned pa[4][4];
        {
            const __nv_bfloat16* pr = &Ps[(w*16 + grp) * PSTRb];
            #pragma unroll
            for (int kc = 0; kc < 4; ++kc) {
                pa[kc][0] = *(const unsigned*)&pr[kc*16 + 2*tig];
                pa[kc][1] = *(const unsigned*)&pr[8*PSTRb + kc*16 + 2*tig];
                pa[kc][2] = *(const unsigned*)&pr[kc*16 + 8 + 2*tig];
                pa[kc][3] = *(const unsigned*)&pr[8*PSTRb + kc*16 + 8 + 2*tig];
            }
        }

        // ---- PV: O(16x64) += P(16x64) V(64x64) ----
        #pragma unroll
        for (int kc = 0; kc < 4; ++kc) {
            #pragma unroll
            for (int np = 0; np < 4; ++np) {
                unsigned d0, d1, d2, d3;
                const unsigned addr = vbuf + (unsigned)(
                    ((kc*16 + ((lane >> 3) & 1) * 8 + (lane & 7)) * KSTRb
                     + np*16 + (lane >> 4) * 8) * 2);
                ldsm_x4_t(d0, d1, d2, d3, addr);
                mma_bf16(of[2*np],     pa[kc], d0, d1);
                mma_bf16(of[2*np + 1], pa[kc], d2, d3);
            }
        }
        __syncthreads();
    }

    const float inv0 = 1.f / l0;
    const float inv1 = 1.f / l1;
    __half* ob = O + (size_t)(q0 + w*16 + grp) * DM + h * DH;
    #pragma unroll
    for (int n = 0; n < 8; ++n) {
        *(unsigned*)&ob[n*8 + 2*tig] =
            pack_f16(of[n][0] * inv0, of[n][1] * inv0);
        *(unsigned*)&ob[(size_t)8 * DM + n*8 + 2*tig] =
            pack_f16(of[n][2] * inv1, of[n][3] * inv1);
    }
}

// ---------------------------------------------------------------------------
// out = LayerNorm(A + B) * gamma + beta.  One block per row.
// DUAL: also write an fp16 copy (for downstream fp16 GEMM A-operand).
// ---------------------------------------------------------------------------
template<bool DUAL>
__global__ void __launch_bounds__(128)
add_ln_kernel(const float* __restrict__ A, const float* __restrict__ B,
              const float* __restrict__ gamma, const float* __restrict__ beta,
              float* __restrict__ O, __half* __restrict__ Oh)
{
    __shared__ float red[4];
    const int row = blockIdx.x;
    const int t   = threadIdx.x;
    const int wid = t >> 5;
    const int lane = t & 31;

    const size_t base = (size_t)row * DM + t * 4;
    float4 a = *(const float4*)(A + base);
    float4 b = *(const float4*)(B + base);
    float4 v = make_float4(a.x + b.x, a.y + b.y, a.z + b.z, a.w + b.w);

    float s = v.x + v.y + v.z + v.w;
    #pragma unroll
    for (int o = 16; o > 0; o >>= 1) s += __shfl_xor_sync(0xffffffffu, s, o);
    if (lane == 0) red[wid] = s;
    __syncthreads();
    const float mu = (red[0] + red[1] + red[2] + red[3]) * (1.f / DM);

    float4 d = make_float4(v.x - mu, v.y - mu, v.z - mu, v.w - mu);
    float ss = d.x*d.x + d.y*d.y + d.z*d.z + d.w*d.w;
    #pragma unroll
    for (int o = 16; o > 0; o >>= 1) ss += __shfl_xor_sync(0xffffffffu, ss, o);
    __syncthreads();
    if (lane == 0) red[wid] = ss;
    __syncthreads();
    const float var  = (red[0] + red[1] + red[2] + red[3]) * (1.f / DM);
    const float rstd = rsqrtf(var + 1e-6f);

    float4 g  = *(const float4*)(gamma + t * 4);
    float4 be = *(const float4*)(beta  + t * 4);
    float4 o;
    o.x = d.x * rstd * g.x + be.x;
    o.y = d.y * rstd * g.y + be.y;
    o.z = d.z * rstd * g.z + be.z;
    o.w = d.w * rstd * g.w + be.w;
    *(float4*)(O + base) = o;
    if (DUAL) {
        unsigned lo = pack_f16(o.x, o.y);
        unsigned hi = pack_f16(o.z, o.w);
        *(uint2*)(Oh + base) = make_uint2(lo, hi);
    }
}

// ---------------------------------------------------------------------------
// kernel_launch
// ---------------------------------------------------------------------------
extern "C" void kernel_launch(void* const* d_in, const int* in_sizes, int n_in,
                              void* d_out, int out_size)
{
    const float* x       = (const float*)d_in[0];
    const float* wq_w    = (const float*)d_in[1];
    const float* wq_b    = (const float*)d_in[2];
    const float* wk_w    = (const float*)d_in[3];
    const float* wk_b    = (const float*)d_in[4];
    const float* wv_w    = (const float*)d_in[5];
    const float* wv_b    = (const float*)d_in[6];
    const float* dense_w = (const float*)d_in[7];
    const float* dense_b = (const float*)d_in[8];
    const float* l1_w    = (const float*)d_in[9];
    const float* l1_b    = (const float*)d_in[10];
    const float* l2_w    = (const float*)d_in[11];
    const float* l2_b    = (const float*)d_in[12];
    const float* ln1_g   = (const float*)d_in[13];
    const float* ln1_b   = (const float*)d_in[14];
    const float* ln2_g   = (const float*)d_in[15];
    const float* ln2_b   = (const float*)d_in[16];
    float* out = (float*)d_out;

    __half *xh, *wqh, *wkh, *wvh, *dwh, *l1h, *l2h, *CTXh, *O1h, *Hh;
    __nv_bfloat16 *Qb, *Kb, *Vb;
    float *ATT, *O1, *F;
    cudaGetSymbolAddress((void**)&xh,   g_xh);
    cudaGetSymbolAddress((void**)&wqh,  g_wqh);
    cudaGetSymbolAddress((void**)&wkh,  g_wkh);
    cudaGetSymbolAddress((void**)&wvh,  g_wvh);
    cudaGetSymbolAddress((void**)&dwh,  g_dwh);
    cudaGetSymbolAddress((void**)&l1h,  g_l1h);
    cudaGetSymbolAddress((void**)&l2h,  g_l2h);
    cudaGetSymbolAddress((void**)&Qb,   g_Qb);
    cudaGetSymbolAddress((void**)&Kb,   g_Kb);
    cudaGetSymbolAddress((void**)&Vb,   g_Vb);
    cudaGetSymbolAddress((void**)&CTXh, g_CTXh);
    cudaGetSymbolAddress((void**)&O1h,  g_O1h);
    cudaGetSymbolAddress((void**)&Hh,   g_Hh);
    cudaGetSymbolAddress((void**)&ATT,  g_ATT);
    cudaGetSymbolAddress((void**)&O1,   g_O1);
    cudaGetSymbolAddress((void**)&F,    g_F);

    // fp32 -> fp16 conversions, single merged launch
    f2h_all_kernel<<<5120, 256>>>(x, xh, wq_w, wqh, wk_w, wkh, wv_w, wvh,
                                  dense_w, dwh, l1_w, l1h, l2_w, l2h);

    // QKV projections, batched. Q scale = (1/sqrt(64)) * log2(e) for exp2 softmax.
    gemm_f16_kernel<false, 1><<<dim3(DM/128, S_LEN/128, 3), 256>>>(
        xh,
        wqh, wq_b, Qb,
        wkh, wk_b, Kb,
        wvh, wv_b, Vb,
        DM, DM, 0.125f * 1.44269504088896f, 1.f, 1.f);

    // attention (bf16 tensor cores, BKV=64; fp16 CTX out)
    flash_attn_bf16_kernel<<<dim3(S_LEN / 64, NH), 128>>>(Qb, Kb, Vb, CTXh);

    // dense proj (BM=128) + add&norm (O1 dual fp32/fp16)
    gemm_f16_kernel<false, 0><<<dim3(DM/128, S_LEN/128, 1), 256>>>(
        CTXh,
        dwh, dense_b, ATT,
        dwh, dense_b, ATT,
        dwh, dense_b, ATT,
        DM, DM, 1.f, 1.f, 1.f);
    add_ln_kernel<true><<<S_LEN, 128>>>(x, ATT, ln1_g, ln1_b, O1, O1h);

    // FFN1 (BM=128, H fp16) ; FFN2 (BM=128) ; add&norm
    gemm_f16_kernel<true, 2><<<dim3(DFF_/128, S_LEN/128, 1), 256>>>(
        O1h,
        l1h, l1_b, Hh,
        l1h, l1_b, Hh,
        l1h, l1_b, Hh,
        DFF_, DM, 1.f, 1.f, 1.f);
    gemm_f16_kernel<false, 0><<<dim3(DM/128, S_LEN/128, 1), 256>>>(
        Hh,
        l2h, l2_b, F,
        l2h, l2_b, F,
        l2h, l2_b, F,
        DM, DFF_, 1.f, 1.f, 1.f);
    add_ln_kernel<false><<<S_LEN, 128>>>(O1, F, ln2_g, ln2_b, out, (__half*)0);
}

// round 12
// speedup vs baseline: 1.0072x; 1.0072x over previous
#include <cuda_runtime.h>
#include <cuda_bf16.h>
#include <cuda_fp16.h>
#include <math.h>

// ---------------------------------------------------------------------------
// EncoderLayer: x[1,4096,512] -> full transformer encoder layer.
//   fp16 (m16n8k16) tensor-core GEMMs (split-K for grid-starved shapes) +
//   bf16 flash attention (BKV=64, exp2 softmax).
// ---------------------------------------------------------------------------

#define S_LEN 4096
#define DM    512
#define DFF_  2048
#define NH    8
#define DH    64

// Scratch (device globals: no allocation allowed in kernel_launch)
__device__ __half g_xh [S_LEN * DM];
__device__ __half g_wqh[DM * DM];
__device__ __half g_wkh[DM * DM];
__device__ __half g_wvh[DM * DM];
__device__ __half g_dwh[DM * DM];
__device__ __half g_l1h[DFF_ * DM];
__device__ __half g_l2h[DM * DFF_];
__device__ __nv_bfloat16 g_Qb[S_LEN * DM];
__device__ __nv_bfloat16 g_Kb[S_LEN * DM];
__device__ __nv_bfloat16 g_Vb[S_LEN * DM];
__device__ __half g_CTXh[S_LEN * DM];
__device__ __half g_O1h [S_LEN * DM];
__device__ __half g_Hh  [S_LEN * DFF_];
__device__ float g_ATT[2 * S_LEN * DM];   // 2 split-K partials
__device__ float g_O1 [S_LEN * DM];
__device__ float g_F  [4 * S_LEN * DM];   // 4 split-K partials

// ---------------------------------------------------------------------------
// PTX helpers
// ---------------------------------------------------------------------------
__device__ __forceinline__ void mma_bf16(float* c, const unsigned* a,
                                         unsigned b0, unsigned b1) {
    asm volatile(
        "mma.sync.aligned.m16n8k16.row.col.f32.bf16.bf16.f32 "
        "{%0,%1,%2,%3}, {%4,%5,%6,%7}, {%8,%9}, {%0,%1,%2,%3};"
        : "+f"(c[0]), "+f"(c[1]), "+f"(c[2]), "+f"(c[3])
        : "r"(a[0]), "r"(a[1]), "r"(a[2]), "r"(a[3]), "r"(b0), "r"(b1));
}

__device__ __forceinline__ void mma_f16(float* c, const unsigned* a,
                                        unsigned b0, unsigned b1) {
    asm volatile(
        "mma.sync.aligned.m16n8k16.row.col.f32.f16.f16.f32 "
        "{%0,%1,%2,%3}, {%4,%5,%6,%7}, {%8,%9}, {%0,%1,%2,%3};"
        : "+f"(c[0]), "+f"(c[1]), "+f"(c[2]), "+f"(c[3])
        : "r"(a[0]), "r"(a[1]), "r"(a[2]), "r"(a[3]), "r"(b0), "r"(b1));
}

__device__ __forceinline__ void ldsm_x4(unsigned& d0, unsigned& d1,
                                        unsigned& d2, unsigned& d3, unsigned addr) {
    asm volatile("ldmatrix.sync.aligned.m8n8.x4.shared.b16 {%0,%1,%2,%3}, [%4];"
                 : "=r"(d0), "=r"(d1), "=r"(d2), "=r"(d3) : "r"(addr));
}

__device__ __forceinline__ void ldsm_x4_t(unsigned& d0, unsigned& d1,
                                          unsigned& d2, unsigned& d3, unsigned addr) {
    asm volatile("ldmatrix.sync.aligned.m8n8.x4.trans.shared.b16 {%0,%1,%2,%3}, [%4];"
                 : "=r"(d0), "=r"(d1), "=r"(d2), "=r"(d3) : "r"(addr));
}

__device__ __forceinline__ unsigned pack_bf16(float lo, float hi) {
    unsigned r;
    asm("cvt.rn.bf16x2.f32 %0, %1, %2;" : "=r"(r) : "f"(hi), "f"(lo));
    return r;
}

__device__ __forceinline__ unsigned pack_f16(float lo, float hi) {
    unsigned r;
    asm("{\n\t.reg .f16 l, h;\n\tcvt.rn.f16.f32 l, %1;\n\tcvt.rn.f16.f32 h, %2;\n\t"
        "mov.b32 %0, {l, h};\n\t}" : "=r"(r) : "f"(lo), "f"(hi));
    return r;
}

__device__ __forceinline__ float ex2(float x) {
    float r;
    asm("ex2.approx.f32 %0, %1;" : "=f"(r) : "f"(x));
    return r;
}

__device__ __forceinline__ void cp16(unsigned dst, const void* src) {
    asm volatile("cp.async.cg.shared.global [%0], [%1], 16;"
                 :: "r"(dst), "l"(src));
}

// ---------------------------------------------------------------------------
// Merged f32 -> f16 convert: all 7 tensors in ONE launch (5120 blocks).
// ---------------------------------------------------------------------------
__global__ void __launch_bounds__(256)
f2h_all_kernel(const float* __restrict__ x,  __half* __restrict__ xh,
               const float* __restrict__ wq, __half* __restrict__ wqh,
               const float* __restrict__ wk, __half* __restrict__ wkh,
               const float* __restrict__ wv, __half* __restrict__ wvh,
               const float* __restrict__ dw, __half* __restrict__ dwh,
               const float* __restrict__ l1, __half* __restrict__ l1h,
               const float* __restrict__ l2, __half* __restrict__ l2h)
{
    int b = blockIdx.x;
    const float* src; __half* dst; int lb;
    if      (b < 2048) { src = x;  dst = xh;  lb = b; }
    else if (b < 2304) { src = wq; dst = wqh; lb = b - 2048; }
    else if (b < 2560) { src = wk; dst = wkh; lb = b - 2304; }
    else if (b < 2816) { src = wv; dst = wvh; lb = b - 2560; }
    else if (b < 3072) { src = dw; dst = dwh; lb = b - 2816; }
    else if (b < 4096) { src = l1; dst = l1h; lb = b - 3072; }
    else               { src = l2; dst = l2h; lb = b - 4096; }
    int i = (lb * 256 + threadIdx.x) * 4;
    float4 v = *(const float4*)(src + i);
    *(uint2*)(dst + i) = make_uint2(pack_f16(v.x, v.y), pack_f16(v.z, v.w));
}

// ---------------------------------------------------------------------------
// fp16 tensor-core NT GEMM: C = (A * W^T + bias) * scale (+ReLU).
// Block tile 128x128, BK=32 fp16, 256 threads, double-buffered cp.async,
// ldmatrix fragments.  OUT: 0 = fp32, 1 = bf16, 2 = fp16.
// SPLITK == 1: blockIdx.z selects among up to 3 weight/bias/output sets.
// SPLITK  > 1: blockIdx.z = K-slice; each slice writes an fp32 partial at
//              C + z*M*N (bias folded into slice 0 only); downstream LN sums.
// ---------------------------------------------------------------------------
#define HSTR 40
#define HTILE (128 * HSTR)   // fp16 units per tile

template<bool RELU, int OUT, int SPLITK>
__global__ void __launch_bounds__(256)
gemm_f16_kernel(const __half* __restrict__ A,
                const __half* __restrict__ W0, const float* __restrict__ bi0, void* __restrict__ C0,
                const __half* __restrict__ W1, const float* __restrict__ bi1, void* __restrict__ C1,
                const __half* __restrict__ W2, const float* __restrict__ bi2, void* __restrict__ C2,
                int N, int K, float s0, float s1, float s2)
{
    __shared__ __half As[2][HTILE];   // 20480 B
    __shared__ __half Bs[2][HTILE];   // 20480 B

    const __half* B    = W0;
    const float*  bias = bi0;
    void*         Cv   = C0;
    float         scl  = s0;
    int           kslice = 0;
    if (SPLITK > 1) {
        kslice = blockIdx.z;
    } else {
        if (blockIdx.z == 1) { B = W1; bias = bi1; Cv = C1; scl = s1; }
        if (blockIdx.z == 2) { B = W2; bias = bi2; Cv = C2; scl = s2; }
    }
    const int KS = (SPLITK > 1) ? (K / SPLITK) : K;

    const int t    = threadIdx.x;
    const int w    = t >> 5;
    const int lane = t & 31;
    const int grp  = lane >> 2;
    const int tig  = lane & 3;
    const int wm   = w >> 2;      // 0..1 : 64-row half
    const int wn   = w & 3;       // 0..3 : 32-col quarter
    const int m0   = blockIdx.y * 128;
    const int n0   = blockIdx.x * 128;
    const int NC   = KS >> 5;     // K-chunks of 32

    // split-K: offset operands into the k-slice; partial output buffer
    const __half* Ak = A + (size_t)kslice * KS;
    const __half* Bk = B + (size_t)kslice * KS;
    float* Cpart = (float*)Cv;
    if (SPLITK > 1)
        Cpart += (size_t)kslice * (size_t)(gridDim.y * 128) * (size_t)N;

    // loader: thread t -> row t>>1, two 16B chunks (8 fp16 each)
    const int lrow = t >> 1;
    const int lc   = (t & 1) * 2;

    const unsigned aB = (unsigned)__cvta_generic_to_shared(&As[0][0]);
    const unsigned bB = (unsigned)__cvta_generic_to_shared(&Bs[0][0]);

    float acc[4][4][4];
    #pragma unroll
    for (int i = 0; i < 4; ++i)
        #pragma unroll
        for (int j = 0; j < 4; ++j)
            #pragma unroll
            for (int c = 0; c < 4; ++c) acc[i][j][c] = 0.f;

    #define HGLOAD(KT, BUF)                                                     \
        {                                                                       \
            const __half* a = Ak + (size_t)(m0 + lrow) * K + (KT) + lc * 8;     \
            const __half* b = Bk + (size_t)(n0 + lrow) * K + (KT) + lc * 8;     \
            const unsigned ad = aB + (unsigned)(((BUF)*HTILE + lrow*HSTR + lc*8) * 2); \
            const unsigned bd = bB + (unsigned)(((BUF)*HTILE + lrow*HSTR + lc*8) * 2); \
            cp16(ad,       a);                                                  \
            cp16(ad + 16u, a + 8);                                              \
            cp16(bd,       b);                                                  \
            cp16(bd + 16u, b + 8);                                              \
        }

    HGLOAD(0, 0);
    asm volatile("cp.async.commit_group;" ::: "memory");

    for (int it = 0; it < NC; ++it) {
        const int buf = it & 1;
        if (it + 1 < NC) {
            HGLOAD((it + 1) << 5, buf ^ 1);
            asm volatile("cp.async.commit_group;" ::: "memory");
            asm volatile("cp.async.wait_group 1;" ::: "memory");
        } else {
            asm volatile("cp.async.wait_group 0;" ::: "memory");
        }
        __syncthreads();

        const unsigned aS = aB + (unsigned)(buf * HTILE * 2);
        const unsigned bS = bB + (unsigned)(buf * HTILE * 2);

        unsigned bf[4][4];
        #pragma unroll
        for (int j = 0; j < 4; ++j)
            ldsm_x4(bf[j][0], bf[j][1], bf[j][2], bf[j][3],
                    bS + (unsigned)(((wn*32 + j*8 + (lane & 7)) * HSTR
                                     + (lane >> 3) * 8) * 2));

        #pragma unroll
        for (int kc = 0; kc < 2; ++kc) {
            unsigned af[4][4];
            #pragma unroll
            for (int i = 0; i < 4; ++i)
                ldsm_x4(af[i][0], af[i][1], af[i][2], af[i][3],
                        aS + (unsigned)(((wm*64 + i*16 + (lane & 15)) * HSTR
                                         + kc*16 + (lane >> 4) * 8) * 2));
            #pragma unroll
            for (int i = 0; i < 4; ++i)
                #pragma unroll
                for (int j = 0; j < 4; ++j)
                    mma_f16(acc[i][j], af[i], bf[j][2*kc], bf[j][2*kc + 1]);
        }
        __syncthreads();
    }
    #undef HGLOAD

    // epilogue: (acc + bias) * scale (+relu); bias only in k-slice 0
    #pragma unroll
    for (int j = 0; j < 4; ++j) {
        const int col = n0 + wn*32 + j*8 + 2*tig;
        float2 bj = make_float2(0.f, 0.f);
        if (SPLITK == 1 || kslice == 0) bj = *(const float2*)&bias[col];
        #pragma unroll
        for (int i = 0; i < 4; ++i) {
            const int row = m0 + wm*64 + i*16 + grp;
            float2 v0 = make_float2((acc[i][j][0] + bj.x) * scl, (acc[i][j][1] + bj.y) * scl);
            float2 v1 = make_float2((acc[i][j][2] + bj.x) * scl, (acc[i][j][3] + bj.y) * scl);
            if (RELU) {
                v0.x = fmaxf(v0.x, 0.f); v0.y = fmaxf(v0.y, 0.f);
                v1.x = fmaxf(v1.x, 0.f); v1.y = fmaxf(v1.y, 0.f);
            }
            if (OUT == 1) {
                __nv_bfloat16* Cb = (__nv_bfloat16*)Cv;
                *(unsigned*)&Cb[(size_t)row       * N + col] = pack_bf16(v0.x, v0.y);
                *(unsigned*)&Cb[(size_t)(row + 8) * N + col] = pack_bf16(v1.x, v1.y);
            } else if (OUT == 2) {
                __half* Ch = (__half*)Cv;
                *(unsigned*)&Ch[(size_t)row       * N + col] = pack_f16(v0.x, v0.y);
                *(unsigned*)&Ch[(size_t)(row + 8) * N + col] = pack_f16(v1.x, v1.y);
            } else {
                *(float2*)&Cpart[(size_t)row       * N + col] = v0;
                *(float2*)&Cpart[(size_t)(row + 8) * N + col] = v1;
            }
        }
    }
}

// ---------------------------------------------------------------------------
// bf16 tensor-core flash attention, BKV=64, exp2-domain softmax (unchanged).
// ---------------------------------------------------------------------------
#define BKV   64
#define NTT   (S_LEN / BKV)   // 64
#define KSTRb 72
#define PSTRb 72

__global__ void __launch_bounds__(128)
flash_attn_bf16_kernel(const __nv_bfloat16* __restrict__ Q,
                       const __nv_bfloat16* __restrict__ K,
                       const __nv_bfloat16* __restrict__ V,
                       __half* __restrict__ O)
{
    __shared__ __nv_bfloat16 Ks[2][BKV * KSTRb];
    __shared__ __nv_bfloat16 Vs[2][BKV * KSTRb];
    __shared__ __nv_bfloat16 Ps[64 * PSTRb];

    const int t    = threadIdx.x;
    const int w    = t >> 5;
    const int lane = t & 31;
    const int grp  = lane >> 2;
    const int tig  = lane & 3;
    const int h    = blockIdx.y;
    const int q0   = blockIdx.x * 64;

    unsigned qa[4][4];
    {
        const __nv_bfloat16* Qb = Q + (size_t)(q0 + w * 16) * DM + h * DH;
        #pragma unroll
        for (int kc = 0; kc < 4; ++kc) {
            qa[kc][0] = *(const unsigned*)&Qb[(size_t)grp       * DM + kc*16 + 2*tig];
            qa[kc][1] = *(const unsigned*)&Qb[(size_t)(grp + 8) * DM + kc*16 + 2*tig];
            qa[kc][2] = *(const unsigned*)&Qb[(size_t)grp       * DM + kc*16 + 8 + 2*tig];
            qa[kc][3] = *(const unsigned*)&Qb[(size_t)(grp + 8) * DM + kc*16 + 8 + 2*tig];
        }
    }

    float of[8][4];
    #pragma unroll
    for (int n = 0; n < 8; ++n)
        #pragma unroll
        for (int c = 0; c < 4; ++c) of[n][c] = 0.f;

    float m0 = -1e30f, m1 = -1e30f, l0 = 0.f, l1 = 0.f;

    const unsigned ksBase = (unsigned)__cvta_generic_to_shared(&Ks[0][0]);
    const unsigned vsBase = (unsigned)__cvta_generic_to_shared(&Vs[0][0]);

    const int lr = t >> 3;
    const int c8 = t & 7;

    #define LOAD_TILE(KB, B)                                                          \
        {                                                                             \
            const size_t krow = (size_t)((KB) * BKV);                                 \
            _Pragma("unroll")                                                         \
            for (int i = 0; i < 4; ++i) {                                             \
                const int r = lr + 16 * i;                                            \
                cp16(ksBase + (unsigned)((((B)*BKV + r)*KSTRb + c8*8) * 2),           \
                     K + (krow + r) * DM + h * DH + c8 * 8);                          \
                cp16(vsBase + (unsigned)((((B)*BKV + r)*KSTRb + c8*8) * 2),           \
                     V + (krow + r) * DM + h * DH + c8 * 8);                          \
            }                                                                         \
        }

    LOAD_TILE(0, 0);
    asm volatile("cp.async.commit_group;" ::: "memory");

    for (int kb = 0; kb < NTT; ++kb) {
        const int buf = kb & 1;
        if (kb + 1 < NTT) {
            LOAD_TILE(kb + 1, buf ^ 1);
            asm volatile("cp.async.commit_group;" ::: "memory");
            asm volatile("cp.async.wait_group 1;" ::: "memory");
        } else {
            asm volatile("cp.async.wait_group 0;" ::: "memory");
        }
        __syncthreads();

        const unsigned kbuf = ksBase + (unsigned)(buf * BKV * KSTRb * 2);
        const unsigned vbuf = vsBase + (unsigned)(buf * BKV * KSTRb * 2);

        float sf[8][4];
        #pragma unroll
        for (int n = 0; n < 8; ++n) {
            sf[n][0] = sf[n][1] = sf[n][2] = sf[n][3] = 0.f;
            #pragma unroll
            for (int kcp = 0; kcp < 2; ++kcp) {
                unsigned d0, d1, d2, d3;
                const unsigned addr = kbuf +
                    (unsigned)(((n*8 + (lane & 7)) * KSTRb + kcp*32 + (lane >> 3) * 8) * 2);
                ldsm_x4(d0, d1, d2, d3, addr);
                mma_bf16(sf[n], qa[2*kcp],     d0, d1);
                mma_bf16(sf[n], qa[2*kcp + 1], d2, d3);
            }
        }

        float mx0 = -1e30f, mx1 = -1e30f;
        #pragma unroll
        for (int n = 0; n < 8; ++n) {
            mx0 = fmaxf(mx0, fmaxf(sf[n][0], sf[n][1]));
            mx1 = fmaxf(mx1, fmaxf(sf[n][2], sf[n][3]));
        }
        mx0 = fmaxf(mx0, __shfl_xor_sync(0xffffffffu, mx0, 1));
        mx0 = fmaxf(mx0, __shfl_xor_sync(0xffffffffu, mx0, 2));
        mx1 = fmaxf(mx1, __shfl_xor_sync(0xffffffffu, mx1, 1));
        mx1 = fmaxf(mx1, __shfl_xor_sync(0xffffffffu, mx1, 2));

        const float mn0 = fmaxf(m0, mx0);
        const float mn1 = fmaxf(m1, mx1);
        const float al0 = ex2(m0 - mn0);
        const float al1 = ex2(m1 - mn1);

        float s0 = 0.f, s1 = 0.f;
        #pragma unroll
        for (int n = 0; n < 8; ++n) {
            sf[n][0] = ex2(sf[n][0] - mn0); s0 += sf[n][0];
            sf[n][1] = ex2(sf[n][1] - mn0); s0 += sf[n][1];
            sf[n][2] = ex2(sf[n][2] - mn1); s1 += sf[n][2];
            sf[n][3] = ex2(sf[n][3] - mn1); s1 += sf[n][3];
        }
        s0 += __shfl_xor_sync(0xffffffffu, s0, 1);
        s0 += __shfl_xor_sync(0xffffffffu, s0, 2);
        s1 += __shfl_xor_sync(0xffffffffu, s1, 1);
        s1 += __shfl_xor_sync(0xffffffffu, s1, 2);

        l0 = l0 * al0 + s0;  m0 = mn0;
        l1 = l1 * al1 + s1;  m1 = mn1;

        #pragma unroll
        for (int n = 0; n < 8; ++n) {
            of[n][0] *= al0; of[n][1] *= al0;
            of[n][2] *= al1; of[n][3] *= al1;
        }

        {
            __nv_bfloat16* pr = &Ps[(w*16 + grp) * PSTRb];
            #pragma unroll
            for (int n = 0; n < 8; ++n) {
                *(unsigned*)&pr[n*8 + 2*tig]           = pack_bf16(sf[n][0], sf[n][1]);
                *(unsigned*)&pr[8*PSTRb + n*8 + 2*tig] = pack_bf16(sf[n][2], sf[n][3]);
            }
        }
        __syncwarp();

        unsigned pa[4][4];
        {
            const __nv_bfloat16* pr = &Ps[(w*16 + grp) * PSTRb];
            #pragma unroll
            for (int kc = 0; kc < 4; ++kc) {
                pa[kc][0] = *(const unsigned*)&pr[kc*16 + 2*tig];
                pa[kc][1] = *(const unsigned*)&pr[8*PSTRb + kc*16 + 2*tig];
                pa[kc][2] = *(const unsigned*)&pr[kc*16 + 8 + 2*tig];
                pa[kc][3] = *(const unsigned*)&pr[8*PSTRb + kc*16 + 8 + 2*tig];
            }
        }

        #pragma unroll
        for (int kc = 0; kc < 4; ++kc) {
            #pragma unroll
            for (int np = 0; np < 4; ++np) {
                unsigned d0, d1, d2, d3;
                const unsigned addr = vbuf + (unsigned)(
                    ((kc*16 + ((lane >> 3) & 1) * 8 + (lane & 7)) * KSTRb
                     + np*16 + (lane >> 4) * 8) * 2);
                ldsm_x4_t(d0, d1, d2, d3, addr);
                mma_bf16(of[2*np],     pa[kc], d0, d1);
                mma_bf16(of[2*np + 1], pa[kc], d2, d3);
            }
        }
        __syncthreads();
    }

    const float inv0 = 1.f / l0;
    const float inv1 = 1.f / l1;
    __half* ob = O + (size_t)(q0 + w*16 + grp) * DM + h * DH;
    #pragma unroll
    for (int n = 0; n < 8; ++n) {
        *(unsigned*)&ob[n*8 + 2*tig] =
            pack_f16(of[n][0] * inv0, of[n][1] * inv0);
        *(unsigned*)&ob[(size_t)8 * DM + n*8 + 2*tig] =
            pack_f16(of[n][2] * inv1, of[n][3] * inv1);
    }
}

// ---------------------------------------------------------------------------
// out = LayerNorm(A + sum of NB partials of B) * gamma + beta. One block/row.
// DUAL: also write an fp16 copy. Partials are at B + p * S_LEN * DM.
// ---------------------------------------------------------------------------
template<int NB, bool DUAL>
__global__ void __launch_bounds__(128)
add_ln_kernel(const float* __restrict__ A, const float* __restrict__ B,
              const float* __restrict__ gamma, const float* __restrict__ beta,
              float* __restrict__ O, __half* __restrict__ Oh)
{
    __shared__ float red[4];
    const int row = blockIdx.x;
    const int t   = threadIdx.x;
    const int wid = t >> 5;
    const int lane = t & 31;

    const size_t base = (size_t)row * DM + t * 4;
    float4 v = *(const float4*)(A + base);
    #pragma unroll
    for (int p = 0; p < NB; ++p) {
        float4 b = *(const float4*)(B + (size_t)p * S_LEN * DM + base);
        v.x += b.x; v.y += b.y; v.z += b.z; v.w += b.w;
    }

    float s = v.x + v.y + v.z + v.w;
    #pragma unroll
    for (int o = 16; o > 0; o >>= 1) s += __shfl_xor_sync(0xffffffffu, s, o);
    if (lane == 0) red[wid] = s;
    __syncthreads();
    const float mu = (red[0] + red[1] + red[2] + red[3]) * (1.f / DM);

    float4 d = make_float4(v.x - mu, v.y - mu, v.z - mu, v.w - mu);
    float ss = d.x*d.x + d.y*d.y + d.z*d.z + d.w*d.w;
    #pragma unroll
    for (int o = 16; o > 0; o >>= 1) ss += __shfl_xor_sync(0xffffffffu, ss, o);
    __syncthreads();
    if (lane == 0) red[wid] = ss;
    __syncthreads();
    const float var  = (red[0] + red[1] + red[2] + red[3]) * (1.f / DM);
    const float rstd = rsqrtf(var + 1e-6f);

    float4 g  = *(const float4*)(gamma + t * 4);
    float4 be = *(const float4*)(beta  + t * 4);
    float4 o;
    o.x = d.x * rstd * g.x + be.x;
    o.y = d.y * rstd * g.y + be.y;
    o.z = d.z * rstd * g.z + be.z;
    o.w = d.w * rstd * g.w + be.w;
    *(float4*)(O + base) = o;
    if (DUAL) {
        unsigned lo = pack_f16(o.x, o.y);
        unsigned hi = pack_f16(o.z, o.w);
        *(uint2*)(Oh + base) = make_uint2(lo, hi);
    }
}

// ---------------------------------------------------------------------------
// kernel_launch
// ---------------------------------------------------------------------------
extern "C" void kernel_launch(void* const* d_in, const int* in_sizes, int n_in,
                              void* d_out, int out_size)
{
    const float* x       = (const float*)d_in[0];
    const float* wq_w    = (const float*)d_in[1];
    const float* wq_b    = (const float*)d_in[2];
    const float* wk_w    = (const float*)d_in[3];
    const float* wk_b    = (const float*)d_in[4];
    const float* wv_w    = (const float*)d_in[5];
    const float* wv_b    = (const float*)d_in[6];
    const float* dense_w = (const float*)d_in[7];
    const float* dense_b = (const float*)d_in[8];
    const float* l1_w    = (const float*)d_in[9];
    const float* l1_b    = (const float*)d_in[10];
    const float* l2_w    = (const float*)d_in[11];
    const float* l2_b    = (const float*)d_in[12];
    const float* ln1_g   = (const float*)d_in[13];
    const float* ln1_b   = (const float*)d_in[14];
    const float* ln2_g   = (const float*)d_in[15];
    const float* ln2_b   = (const float*)d_in[16];
    float* out = (float*)d_out;

    __half *xh, *wqh, *wkh, *wvh, *dwh, *l1h, *l2h, *CTXh, *O1h, *Hh;
    __nv_bfloat16 *Qb, *Kb, *Vb;
    float *ATT, *O1, *F;
    cudaGetSymbolAddress((void**)&xh,   g_xh);
    cudaGetSymbolAddress((void**)&wqh,  g_wqh);
    cudaGetSymbolAddress((void**)&wkh,  g_wkh);
    cudaGetSymbolAddress((void**)&wvh,  g_wvh);
    cudaGetSymbolAddress((void**)&dwh,  g_dwh);
    cudaGetSymbolAddress((void**)&l1h,  g_l1h);
    cudaGetSymbolAddress((void**)&l2h,  g_l2h);
    cudaGetSymbolAddress((void**)&Qb,   g_Qb);
    cudaGetSymbolAddress((void**)&Kb,   g_Kb);
    cudaGetSymbolAddress((void**)&Vb,   g_Vb);
    cudaGetSymbolAddress((void**)&CTXh, g_CTXh);
    cudaGetSymbolAddress((void**)&O1h,  g_O1h);
    cudaGetSymbolAddress((void**)&Hh,   g_Hh);
    cudaGetSymbolAddress((void**)&ATT,  g_ATT);
    cudaGetSymbolAddress((void**)&O1,   g_O1);
    cudaGetSymbolAddress((void**)&F,    g_F);

    // fp32 -> fp16 conversions, single merged launch
    f2h_all_kernel<<<5120, 256>>>(x, xh, wq_w, wqh, wk_w, wkh, wv_w, wvh,
                                  dense_w, dwh, l1_w, l1h, l2_w, l2h);

    // QKV projections, batched. Q scale = (1/sqrt(64)) * log2(e) for exp2 softmax.
    gemm_f16_kernel<false, 1, 1><<<dim3(DM/128, S_LEN/128, 3), 256>>>(
        xh,
        wqh, wq_b, Qb,
        wkh, wk_b, Kb,
        wvh, wv_b, Vb,
        DM, DM, 0.125f * 1.44269504088896f, 1.f, 1.f);

    // attention (bf16 tensor cores, BKV=64; fp16 CTX out)
    flash_attn_bf16_kernel<<<dim3(S_LEN / 64, NH), 128>>>(Qb, Kb, Vb, CTXh);

    // dense proj: split-K=2 (grid 256 CTAs, fp32 partials) + fused-reduce LN
    gemm_f16_kernel<false, 0, 2><<<dim3(DM/128, S_LEN/128, 2), 256>>>(
        CTXh,
        dwh, dense_b, ATT,
        dwh, dense_b, ATT,
        dwh, dense_b, ATT,
        DM, DM, 1.f, 1.f, 1.f);
    add_ln_kernel<2, true><<<S_LEN, 128>>>(x, ATT, ln1_g, ln1_b, O1, O1h);

    // FFN1 (grid 512, H fp16)
    gemm_f16_kernel<true, 2, 1><<<dim3(DFF_/128, S_LEN/128, 1), 256>>>(
        O1h,
        l1h, l1_b, Hh,
        l1h, l1_b, Hh,
        l1h, l1_b, Hh,
        DFF_, DM, 1.f, 1.f, 1.f);

    // FFN2: split-K=4 (grid 512 CTAs, fp32 partials) + fused-reduce LN
    gemm_f16_kernel<false, 0, 4><<<dim3(DM/128, S_LEN/128, 4), 256>>>(
        Hh,
        l2h, l2_b, F,
        l2h, l2_b, F,
        l2h, l2_b, F,
        DM, DFF_, 1.f, 1.f, 1.f);
    add_ln_kernel<4, false><<<S_LEN, 128>>>(O1, F, ln2_g, ln2_b, out, (__half*)0);
}

// round 13
// speedup vs baseline: 1.0145x; 1.0072x over previous
#include <cuda_runtime.h>
#include <cuda_bf16.h>
#include <cuda_fp16.h>
#include <math.h>

// ---------------------------------------------------------------------------
// EncoderLayer: x[1,4096,512] -> full transformer encoder layer.
//   fp16 (m16n8k16) tensor-core GEMMs (split-K with fp16 partials) +
//   bf16 flash attention (BKV=64, exp2 softmax).
// ---------------------------------------------------------------------------

#define S_LEN 4096
#define DM    512
#define DFF_  2048
#define NH    8
#define DH    64

// Scratch (device globals: no allocation allowed in kernel_launch)
__device__ __half g_xh [S_LEN * DM];
__device__ __half g_wqh[DM * DM];
__device__ __half g_wkh[DM * DM];
__device__ __half g_wvh[DM * DM];
__device__ __half g_dwh[DM * DM];
__device__ __half g_l1h[DFF_ * DM];
__device__ __half g_l2h[DM * DFF_];
__device__ __nv_bfloat16 g_Qb[S_LEN * DM];
__device__ __nv_bfloat16 g_Kb[S_LEN * DM];
__device__ __nv_bfloat16 g_Vb[S_LEN * DM];
__device__ __half g_CTXh[S_LEN * DM];
__device__ __half g_O1h [S_LEN * DM];
__device__ __half g_Hh  [S_LEN * DFF_];
__device__ __half g_ATT[2 * S_LEN * DM];   // 2 split-K fp16 partials
__device__ float  g_O1 [S_LEN * DM];
__device__ __half g_F  [4 * S_LEN * DM];   // 4 split-K fp16 partials

// ---------------------------------------------------------------------------
// PTX helpers
// ---------------------------------------------------------------------------
__device__ __forceinline__ void mma_bf16(float* c, const unsigned* a,
                                         unsigned b0, unsigned b1) {
    asm volatile(
        "mma.sync.aligned.m16n8k16.row.col.f32.bf16.bf16.f32 "
        "{%0,%1,%2,%3}, {%4,%5,%6,%7}, {%8,%9}, {%0,%1,%2,%3};"
        : "+f"(c[0]), "+f"(c[1]), "+f"(c[2]), "+f"(c[3])
        : "r"(a[0]), "r"(a[1]), "r"(a[2]), "r"(a[3]), "r"(b0), "r"(b1));
}

__device__ __forceinline__ void mma_f16(float* c, const unsigned* a,
                                        unsigned b0, unsigned b1) {
    asm volatile(
        "mma.sync.aligned.m16n8k16.row.col.f32.f16.f16.f32 "
        "{%0,%1,%2,%3}, {%4,%5,%6,%7}, {%8,%9}, {%0,%1,%2,%3};"
        : "+f"(c[0]), "+f"(c[1]), "+f"(c[2]), "+f"(c[3])
        : "r"(a[0]), "r"(a[1]), "r"(a[2]), "r"(a[3]), "r"(b0), "r"(b1));
}

__device__ __forceinline__ void ldsm_x4(unsigned& d0, unsigned& d1,
                                        unsigned& d2, unsigned& d3, unsigned addr) {
    asm volatile("ldmatrix.sync.aligned.m8n8.x4.shared.b16 {%0,%1,%2,%3}, [%4];"
                 : "=r"(d0), "=r"(d1), "=r"(d2), "=r"(d3) : "r"(addr));
}

__device__ __forceinline__ void ldsm_x4_t(unsigned& d0, unsigned& d1,
                                          unsigned& d2, unsigned& d3, unsigned addr) {
    asm volatile("ldmatrix.sync.aligned.m8n8.x4.trans.shared.b16 {%0,%1,%2,%3}, [%4];"
                 : "=r"(d0), "=r"(d1), "=r"(d2), "=r"(d3) : "r"(addr));
}

__device__ __forceinline__ unsigned pack_bf16(float lo, float hi) {
    unsigned r;
    asm("cvt.rn.bf16x2.f32 %0, %1, %2;" : "=r"(r) : "f"(hi), "f"(lo));
    return r;
}

__device__ __forceinline__ unsigned pack_f16(float lo, float hi) {
    unsigned r;
    asm("{\n\t.reg .f16 l, h;\n\tcvt.rn.f16.f32 l, %1;\n\tcvt.rn.f16.f32 h, %2;\n\t"
        "mov.b32 %0, {l, h};\n\t}" : "=r"(r) : "f"(lo), "f"(hi));
    return r;
}

__device__ __forceinline__ float2 unpack_f16(unsigned u) {
    __half2 h = *(__half2*)&u;
    return __half22float2(h);
}

__device__ __forceinline__ float ex2(float x) {
    float r;
    asm("ex2.approx.f32 %0, %1;" : "=f"(r) : "f"(x));
    return r;
}

__device__ __forceinline__ void cp16(unsigned dst, const void* src) {
    asm volatile("cp.async.cg.shared.global [%0], [%1], 16;"
                 :: "r"(dst), "l"(src));
}

// ---------------------------------------------------------------------------
// Merged f32 -> f16 convert: all 7 tensors in ONE launch (5120 blocks).
// ---------------------------------------------------------------------------
__global__ void __launch_bounds__(256)
f2h_all_kernel(const float* __restrict__ x,  __half* __restrict__ xh,
               const float* __restrict__ wq, __half* __restrict__ wqh,
               const float* __restrict__ wk, __half* __restrict__ wkh,
               const float* __restrict__ wv, __half* __restrict__ wvh,
               const float* __restrict__ dw, __half* __restrict__ dwh,
               const float* __restrict__ l1, __half* __restrict__ l1h,
               const float* __restrict__ l2, __half* __restrict__ l2h)
{
    int b = blockIdx.x;
    const float* src; __half* dst; int lb;
    if      (b < 2048) { src = x;  dst = xh;  lb = b; }
    else if (b < 2304) { src = wq; dst = wqh; lb = b - 2048; }
    else if (b < 2560) { src = wk; dst = wkh; lb = b - 2304; }
    else if (b < 2816) { src = wv; dst = wvh; lb = b - 2560; }
    else if (b < 3072) { src = dw; dst = dwh; lb = b - 2816; }
    else if (b < 4096) { src = l1; dst = l1h; lb = b - 3072; }
    else               { src = l2; dst = l2h; lb = b - 4096; }
    int i = (lb * 256 + threadIdx.x) * 4;
    float4 v = *(const float4*)(src + i);
    *(uint2*)(dst + i) = make_uint2(pack_f16(v.x, v.y), pack_f16(v.z, v.w));
}

// ---------------------------------------------------------------------------
// fp16 tensor-core NT GEMM: C = (A * W^T + bias) * scale (+ReLU).
// Block tile 128x128, BK=32 fp16, 256 threads, double-buffered cp.async,
// ldmatrix fragments.  OUT: 0 = fp16 split-K partial, 1 = bf16, 2 = fp16.
// SPLITK == 1: blockIdx.z selects among up to 3 weight/bias/output sets.
// SPLITK  > 1: blockIdx.z = K-slice; each slice writes an fp16 partial at
//              C + z*M*N (bias folded into slice 0 only); downstream LN sums.
// ---------------------------------------------------------------------------
#define HSTR 40
#define HTILE (128 * HSTR)   // fp16 units per tile

template<bool RELU, int OUT, int SPLITK>
__global__ void __launch_bounds__(256)
gemm_f16_kernel(const __half* __restrict__ A,
                const __half* __restrict__ W0, const float* __restrict__ bi0, void* __restrict__ C0,
                const __half* __restrict__ W1, const float* __restrict__ bi1, void* __restrict__ C1,
                const __half* __restrict__ W2, const float* __restrict__ bi2, void* __restrict__ C2,
                int N, int K, float s0, float s1, float s2)
{
    __shared__ __half As[2][HTILE];   // 20480 B
    __shared__ __half Bs[2][HTILE];   // 20480 B

    const __half* B    = W0;
    const float*  bias = bi0;
    void*         Cv   = C0;
    float         scl  = s0;
    int           kslice = 0;
    if (SPLITK > 1) {
        kslice = blockIdx.z;
    } else {
        if (blockIdx.z == 1) { B = W1; bias = bi1; Cv = C1; scl = s1; }
        if (blockIdx.z == 2) { B = W2; bias = bi2; Cv = C2; scl = s2; }
    }
    const int KS = (SPLITK > 1) ? (K / SPLITK) : K;

    const int t    = threadIdx.x;
    const int w    = t >> 5;
    const int lane = t & 31;
    const int grp  = lane >> 2;
    const int tig  = lane & 3;
    const int wm   = w >> 2;      // 0..1 : 64-row half
    const int wn   = w & 3;       // 0..3 : 32-col quarter
    const int m0   = blockIdx.y * 128;
    const int n0   = blockIdx.x * 128;
    const int NC   = KS >> 5;     // K-chunks of 32

    // split-K: offset operands into the k-slice; fp16 partial output buffer
    const __half* Ak = A + (size_t)kslice * KS;
    const __half* Bk = B + (size_t)kslice * KS;
    __half* Cpart = (__half*)Cv;
    if (SPLITK > 1)
        Cpart += (size_t)kslice * (size_t)(gridDim.y * 128) * (size_t)N;

    // loader: thread t -> row t>>1, two 16B chunks (8 fp16 each)
    const int lrow = t >> 1;
    const int lc   = (t & 1) * 2;

    const unsigned aB = (unsigned)__cvta_generic_to_shared(&As[0][0]);
    const unsigned bB = (unsigned)__cvta_generic_to_shared(&Bs[0][0]);

    float acc[4][4][4];
    #pragma unroll
    for (int i = 0; i < 4; ++i)
        #pragma unroll
        for (int j = 0; j < 4; ++j)
            #pragma unroll
            for (int c = 0; c < 4; ++c) acc[i][j][c] = 0.f;

    #define HGLOAD(KT, BUF)                                                     \
        {                                                                       \
            const __half* a = Ak + (size_t)(m0 + lrow) * K + (KT) + lc * 8;     \
            const __half* b = Bk + (size_t)(n0 + lrow) * K + (KT) + lc * 8;     \
            const unsigned ad = aB + (unsigned)(((BUF)*HTILE + lrow*HSTR + lc*8) * 2); \
            const unsigned bd = bB + (unsigned)(((BUF)*HTILE + lrow*HSTR + lc*8) * 2); \
            cp16(ad,       a);                                                  \
            cp16(ad + 16u, a + 8);                                              \
            cp16(bd,       b);                                                  \
            cp16(bd + 16u, b + 8);                                              \
        }

    HGLOAD(0, 0);
    asm volatile("cp.async.commit_group;" ::: "memory");

    for (int it = 0; it < NC; ++it) {
        const int buf = it & 1;
        if (it + 1 < NC) {
            HGLOAD((it + 1) << 5, buf ^ 1);
            asm volatile("cp.async.commit_group;" ::: "memory");
            asm volatile("cp.async.wait_group 1;" ::: "memory");
        } else {
            asm volatile("cp.async.wait_group 0;" ::: "memory");
        }
        __syncthreads();

        const unsigned aS = aB + (unsigned)(buf * HTILE * 2);
        const unsigned bS = bB + (unsigned)(buf * HTILE * 2);

        unsigned bf[4][4];
        #pragma unroll
        for (int j = 0; j < 4; ++j)
            ldsm_x4(bf[j][0], bf[j][1], bf[j][2], bf[j][3],
                    bS + (unsigned)(((wn*32 + j*8 + (lane & 7)) * HSTR
                                     + (lane >> 3) * 8) * 2));

        #pragma unroll
        for (int kc = 0; kc < 2; ++kc) {
            unsigned af[4][4];
            #pragma unroll
            for (int i = 0; i < 4; ++i)
                ldsm_x4(af[i][0], af[i][1], af[i][2], af[i][3],
                        aS + (unsigned)(((wm*64 + i*16 + (lane & 15)) * HSTR
                                         + kc*16 + (lane >> 4) * 8) * 2));
            #pragma unroll
            for (int i = 0; i < 4; ++i)
                #pragma unroll
                for (int j = 0; j < 4; ++j)
                    mma_f16(acc[i][j], af[i], bf[j][2*kc], bf[j][2*kc + 1]);
        }
        __syncthreads();
    }
    #undef HGLOAD

    // epilogue: (acc + bias) * scale (+relu); bias only in k-slice 0
    #pragma unroll
    for (int j = 0; j < 4; ++j) {
        const int col = n0 + wn*32 + j*8 + 2*tig;
        float2 bj = make_float2(0.f, 0.f);
        if (SPLITK == 1 || kslice == 0) bj = *(const float2*)&bias[col];
        #pragma unroll
        for (int i = 0; i < 4; ++i) {
            const int row = m0 + wm*64 + i*16 + grp;
            float2 v0 = make_float2((acc[i][j][0] + bj.x) * scl, (acc[i][j][1] + bj.y) * scl);
            float2 v1 = make_float2((acc[i][j][2] + bj.x) * scl, (acc[i][j][3] + bj.y) * scl);
            if (RELU) {
                v0.x = fmaxf(v0.x, 0.f); v0.y = fmaxf(v0.y, 0.f);
                v1.x = fmaxf(v1.x, 0.f); v1.y = fmaxf(v1.y, 0.f);
            }
            if (OUT == 1) {
                __nv_bfloat16* Cb = (__nv_bfloat16*)Cv;
                *(unsigned*)&Cb[(size_t)row       * N + col] = pack_bf16(v0.x, v0.y);
                *(unsigned*)&Cb[(size_t)(row + 8) * N + col] = pack_bf16(v1.x, v1.y);
            } else if (OUT == 2) {
                __half* Ch = (__half*)Cv;
                *(unsigned*)&Ch[(size_t)row       * N + col] = pack_f16(v0.x, v0.y);
                *(unsigned*)&Ch[(size_t)(row + 8) * N + col] = pack_f16(v1.x, v1.y);
            } else {
                *(unsigned*)&Cpart[(size_t)row       * N + col] = pack_f16(v0.x, v0.y);
                *(unsigned*)&Cpart[(size_t)(row + 8) * N + col] = pack_f16(v1.x, v1.y);
            }
        }
    }
}

// ---------------------------------------------------------------------------
// bf16 tensor-core flash attention, BKV=64, exp2-domain softmax (unchanged).
// ---------------------------------------------------------------------------
#define BKV   64
#define NTT   (S_LEN / BKV)   // 64
#define KSTRb 72
#define PSTRb 72

__global__ void __launch_bounds__(128)
flash_attn_bf16_kernel(const __nv_bfloat16* __restrict__ Q,
                       const __nv_bfloat16* __restrict__ K,
                       const __nv_bfloat16* __restrict__ V,
                       __half* __restrict__ O)
{
    __shared__ __nv_bfloat16 Ks[2][BKV * KSTRb];
    __shared__ __nv_bfloat16 Vs[2][BKV * KSTRb];
    __shared__ __nv_bfloat16 Ps[64 * PSTRb];

    const int t    = threadIdx.x;
    const int w    = t >> 5;
    const int lane = t & 31;
    const int grp  = lane >> 2;
    const int tig  = lane & 3;
    const int h    = blockIdx.y;
    const int q0   = blockIdx.x * 64;

    unsigned qa[4][4];
    {
        const __nv_bfloat16* Qb = Q + (size_t)(q0 + w * 16) * DM + h * DH;
        #pragma unroll
        for (int kc = 0; kc < 4; ++kc) {
            qa[kc][0] = *(const unsigned*)&Qb[(size_t)grp       * DM + kc*16 + 2*tig];
            qa[kc][1] = *(const unsigned*)&Qb[(size_t)(grp + 8) * DM + kc*16 + 2*tig];
            qa[kc][2] = *(const unsigned*)&Qb[(size_t)grp       * DM + kc*16 + 8 + 2*tig];
            qa[kc][3] = *(const unsigned*)&Qb[(size_t)(grp + 8) * DM + kc*16 + 8 + 2*tig];
        }
    }

    float of[8][4];
    #pragma unroll
    for (int n = 0; n < 8; ++n)
        #pragma unroll
        for (int c = 0; c < 4; ++c) of[n][c] = 0.f;

    float m0 = -1e30f, m1 = -1e30f, l0 = 0.f, l1 = 0.f;

    const unsigned ksBase = (unsigned)__cvta_generic_to_shared(&Ks[0][0]);
    const unsigned vsBase = (unsigned)__cvta_generic_to_shared(&Vs[0][0]);

    const int lr = t >> 3;
    const int c8 = t & 7;

    #define LOAD_TILE(KB, B)                                                          \
        {                                                                             \
            const size_t krow = (size_t)((KB) * BKV);                                 \
            _Pragma("unroll")                                                         \
            for (int i = 0; i < 4; ++i) {                                             \
                const int r = lr + 16 * i;                                            \
                cp16(ksBase + (unsigned)((((B)*BKV + r)*KSTRb + c8*8) * 2),           \
                     K + (krow + r) * DM + h * DH + c8 * 8);                          \
                cp16(vsBase + (unsigned)((((B)*BKV + r)*KSTRb + c8*8) * 2),           \
                     V + (krow + r) * DM + h * DH + c8 * 8);                          \
            }                                                                         \
        }

    LOAD_TILE(0, 0);
    asm volatile("cp.async.commit_group;" ::: "memory");

    for (int kb = 0; kb < NTT; ++kb) {
        const int buf = kb & 1;
        if (kb + 1 < NTT) {
            LOAD_TILE(kb + 1, buf ^ 1);
            asm volatile("cp.async.commit_group;" ::: "memory");
            asm volatile("cp.async.wait_group 1;" ::: "memory");
        } else {
            asm volatile("cp.async.wait_group 0;" ::: "memory");
        }
        __syncthreads();

        const unsigned kbuf = ksBase + (unsigned)(buf * BKV * KSTRb * 2);
        const unsigned vbuf = vsBase + (unsigned)(buf * BKV * KSTRb * 2);

        float sf[8][4];
        #pragma unroll
        for (int n = 0; n < 8; ++n) {
            sf[n][0] = sf[n][1] = sf[n][2] = sf[n][3] = 0.f;
            #pragma unroll
            for (int kcp = 0; kcp < 2; ++kcp) {
                unsigned d0, d1, d2, d3;
                const unsigned addr = kbuf +
                    (unsigned)(((n*8 + (lane & 7)) * KSTRb + kcp*32 + (lane >> 3) * 8) * 2);
                ldsm_x4(d0, d1, d2, d3, addr);
                mma_bf16(sf[n], qa[2*kcp],     d0, d1);
                mma_bf16(sf[n], qa[2*kcp + 1], d2, d3);
            }
        }

        float mx0 = -1e30f, mx1 = -1e30f;
        #pragma unroll
        for (int n = 0; n < 8; ++n) {
            mx0 = fmaxf(mx0, fmaxf(sf[n][0], sf[n][1]));
            mx1 = fmaxf(mx1, fmaxf(sf[n][2], sf[n][3]));
        }
        mx0 = fmaxf(mx0, __shfl_xor_sync(0xffffffffu, mx0, 1));
        mx0 = fmaxf(mx0, __shfl_xor_sync(0xffffffffu, mx0, 2));
        mx1 = fmaxf(mx1, __shfl_xor_sync(0xffffffffu, mx1, 1));
        mx1 = fmaxf(mx1, __shfl_xor_sync(0xffffffffu, mx1, 2));

        const float mn0 = fmaxf(m0, mx0);
        const float mn1 = fmaxf(m1, mx1);
        const float al0 = ex2(m0 - mn0);
        const float al1 = ex2(m1 - mn1);

        float s0 = 0.f, s1 = 0.f;
        #pragma unroll
        for (int n = 0; n < 8; ++n) {
            sf[n][0] = ex2(sf[n][0] - mn0); s0 += sf[n][0];
            sf[n][1] = ex2(sf[n][1] - mn0); s0 += sf[n][1];
            sf[n][2] = ex2(sf[n][2] - mn1); s1 += sf[n][2];
            sf[n][3] = ex2(sf[n][3] - mn1); s1 += sf[n][3];
        }
        s0 += __shfl_xor_sync(0xffffffffu, s0, 1);
        s0 += __shfl_xor_sync(0xffffffffu, s0, 2);
        s1 += __shfl_xor_sync(0xffffffffu, s1, 1);
        s1 += __shfl_xor_sync(0xffffffffu, s1, 2);

        l0 = l0 * al0 + s0;  m0 = mn0;
        l1 = l1 * al1 + s1;  m1 = mn1;

        #pragma unroll
        for (int n = 0; n < 8; ++n) {
            of[n][0] *= al0; of[n][1] *= al0;
            of[n][2] *= al1; of[n][3] *= al1;
        }

        {
            __nv_bfloat16* pr = &Ps[(w*16 + grp) * PSTRb];
            #pragma unroll
            for (int n = 0; n < 8; ++n) {
                *(unsigned*)&pr[n*8 + 2*tig]           = pack_bf16(sf[n][0], sf[n][1]);
                *(unsigned*)&pr[8*PSTRb + n*8 + 2*tig] = pack_bf16(sf[n][2], sf[n][3]);
            }
        }
        __syncwarp();

        unsigned pa[4][4];
        {
            const __nv_bfloat16* pr = &Ps[(w*16 + grp) * PSTRb];
            #pragma unroll
            for (int kc = 0; kc < 4; ++kc) {
                pa[kc][0] = *(const unsigned*)&pr[kc*16 + 2*tig];
                pa[kc][1] = *(const unsigned*)&pr[8*PSTRb + kc*16 + 2*tig];
                pa[kc][2] = *(const unsigned*)&pr[kc*16 + 8 + 2*tig];
                pa[kc][3] = *(const unsigned*)&pr[8*PSTRb + kc*16 + 8 + 2*tig];
            }
        }

        #pragma unroll
        for (int kc = 0; kc < 4; ++kc) {
            #pragma unroll
            for (int np = 0; np < 4; ++np) {
                unsigned d0, d1, d2, d3;
                const unsigned addr = vbuf + (unsigned)(
                    ((kc*16 + ((lane >> 3) & 1) * 8 + (lane & 7)) * KSTRb
                     + np*16 + (lane >> 4) * 8) * 2);
                ldsm_x4_t(d0, d1, d2, d3, addr);
                mma_bf16(of[2*np],     pa[kc], d0, d1);
                mma_bf16(of[2*np + 1], pa[kc], d2, d3);
            }
        }
        __syncthreads();
    }

    const float inv0 = 1.f / l0;
    const float inv1 = 1.f / l1;
    __half* ob = O + (size_t)(q0 + w*16 + grp) * DM + h * DH;
    #pragma unroll
    for (int n = 0; n < 8; ++n) {
        *(unsigned*)&ob[n*8 + 2*tig] =
            pack_f16(of[n][0] * inv0, of[n][1] * inv0);
        *(unsigned*)&ob[(size_t)8 * DM + n*8 + 2*tig] =
            pack_f16(of[n][2] * inv1, of[n][3] * inv1);
    }
}

// ---------------------------------------------------------------------------
// out = LayerNorm(A + sum of NB fp16 partials of B) * gamma + beta.
// One block per row. DUAL: also write an fp16 copy.
// ---------------------------------------------------------------------------
template<int NB, bool DUAL>
__global__ void __launch_bounds__(128)
add_ln_kernel(const float* __restrict__ A, const __half* __restrict__ B,
              const float* __restrict__ gamma, const float* __restrict__ beta,
              float* __restrict__ O, __half* __restrict__ Oh)
{
    __shared__ float red[4];
    const int row = blockIdx.x;
    const int t   = threadIdx.x;
    const int wid = t >> 5;
    const int lane = t & 31;

    const size_t base = (size_t)row * DM + t * 4;
    float4 v = *(const float4*)(A + base);
    #pragma unroll
    for (int p = 0; p < NB; ++p) {
        uint2 bu = *(const uint2*)(B + (size_t)p * S_LEN * DM + base);
        float2 b0 = unpack_f16(bu.x);
        float2 b1 = unpack_f16(bu.y);
        v.x += b0.x; v.y += b0.y; v.z += b1.x; v.w += b1.y;
    }

    float s = v.x + v.y + v.z + v.w;
    #pragma unroll
    for (int o = 16; o > 0; o >>= 1) s += __shfl_xor_sync(0xffffffffu, s, o);
    if (lane == 0) red[wid] = s;
    __syncthreads();
    const float mu = (red[0] + red[1] + red[2] + red[3]) * (1.f / DM);

    float4 d = make_float4(v.x - mu, v.y - mu, v.z - mu, v.w - mu);
    float ss = d.x*d.x + d.y*d.y + d.z*d.z + d.w*d.w;
    #pragma unroll
    for (int o = 16; o > 0; o >>= 1) ss += __shfl_xor_sync(0xffffffffu, ss, o);
    __syncthreads();
    if (lane == 0) red[wid] = ss;
    __syncthreads();
    const float var  = (red[0] + red[1] + red[2] + red[3]) * (1.f / DM);
    const float rstd = rsqrtf(var + 1e-6f);

    float4 g  = *(const float4*)(gamma + t * 4);
    float4 be = *(const float4*)(beta  + t * 4);
    float4 o;
    o.x = d.x * rstd * g.x + be.x;
    o.y = d.y * rstd * g.y + be.y;
    o.z = d.z * rstd * g.z + be.z;
    o.w = d.w * rstd * g.w + be.w;
    *(float4*)(O + base) = o;
    if (DUAL) {
        unsigned lo = pack_f16(o.x, o.y);
        unsigned hi = pack_f16(o.z, o.w);
        *(uint2*)(Oh + base) = make_uint2(lo, hi);
    }
}

// ---------------------------------------------------------------------------
// kernel_launch
// ---------------------------------------------------------------------------
extern "C" void kernel_launch(void* const* d_in, const int* in_sizes, int n_in,
                              void* d_out, int out_size)
{
    const float* x       = (const float*)d_in[0];
    const float* wq_w    = (const float*)d_in[1];
    const float* wq_b    = (const float*)d_in[2];
    const float* wk_w    = (const float*)d_in[3];
    const float* wk_b    = (const float*)d_in[4];
    const float* wv_w    = (const float*)d_in[5];
    const float* wv_b    = (const float*)d_in[6];
    const float* dense_w = (const float*)d_in[7];
    const float* dense_b = (const float*)d_in[8];
    const float* l1_w    = (const float*)d_in[9];
    const float* l1_b    = (const float*)d_in[10];
    const float* l2_w    = (const float*)d_in[11];
    const float* l2_b    = (const float*)d_in[12];
    const float* ln1_g   = (const float*)d_in[13];
    const float* ln1_b   = (const float*)d_in[14];
    const float* ln2_g   = (const float*)d_in[15];
    const float* ln2_b   = (const float*)d_in[16];
    float* out = (float*)d_out;

    __half *xh, *wqh, *wkh, *wvh, *dwh, *l1h, *l2h, *CTXh, *O1h, *Hh, *ATT, *F;
    __nv_bfloat16 *Qb, *Kb, *Vb;
    float *O1;
    cudaGetSymbolAddress((void**)&xh,   g_xh);
    cudaGetSymbolAddress((void**)&wqh,  g_wqh);
    cudaGetSymbolAddress((void**)&wkh,  g_wkh);
    cudaGetSymbolAddress((void**)&wvh,  g_wvh);
    cudaGetSymbolAddress((void**)&dwh,  g_dwh);
    cudaGetSymbolAddress((void**)&l1h,  g_l1h);
    cudaGetSymbolAddress((void**)&l2h,  g_l2h);
    cudaGetSymbolAddress((void**)&Qb,   g_Qb);
    cudaGetSymbolAddress((void**)&Kb,   g_Kb);
    cudaGetSymbolAddress((void**)&Vb,   g_Vb);
    cudaGetSymbolAddress((void**)&CTXh, g_CTXh);
    cudaGetSymbolAddress((void**)&O1h,  g_O1h);
    cudaGetSymbolAddress((void**)&Hh,   g_Hh);
    cudaGetSymbolAddress((void**)&ATT,  g_ATT);
    cudaGetSymbolAddress((void**)&O1,   g_O1);
    cudaGetSymbolAddress((void**)&F,    g_F);

    // fp32 -> fp16 conversions, single merged launch
    f2h_all_kernel<<<5120, 256>>>(x, xh, wq_w, wqh, wk_w, wkh, wv_w, wvh,
                                  dense_w, dwh, l1_w, l1h, l2_w, l2h);

    // QKV projections, batched. Q scale = (1/sqrt(64)) * log2(e) for exp2 softmax.
    gemm_f16_kernel<false, 1, 1><<<dim3(DM/128, S_LEN/128, 3), 256>>>(
        xh,
        wqh, wq_b, Qb,
        wkh, wk_b, Kb,
        wvh, wv_b, Vb,
        DM, DM, 0.125f * 1.44269504088896f, 1.f, 1.f);

    // attention (bf16 tensor cores, BKV=64; fp16 CTX out)
    flash_attn_bf16_kernel<<<dim3(S_LEN / 64, NH), 128>>>(Qb, Kb, Vb, CTXh);

    // dense proj: split-K=2, fp16 partials + fused-reduce LN
    gemm_f16_kernel<false, 0, 2><<<dim3(DM/128, S_LEN/128, 2), 256>>>(
        CTXh,
        dwh, dense_b, ATT,
        dwh, dense_b, ATT,
        dwh, dense_b, ATT,
        DM, DM, 1.f, 1.f, 1.f);
    add_ln_kernel<2, true><<<S_LEN, 128>>>(x, ATT, ln1_g, ln1_b, O1, O1h);

    // FFN1 (grid 512, H fp16)
    gemm_f16_kernel<true, 2, 1><<<dim3(DFF_/128, S_LEN/128, 1), 256>>>(
        O1h,
        l1h, l1_b, Hh,
        l1h, l1_b, Hh,
        l1h, l1_b, Hh,
        DFF_, DM, 1.f, 1.f, 1.f);

    // FFN2: split-K=4, fp16 partials + fused-reduce LN
    gemm_f16_kernel<false, 0, 4><<<dim3(DM/128, S_LEN/128, 4), 256>>>(
        Hh,
        l2h, l2_b, F,
        l2h, l2_b, F,
        l2h, l2_b, F,
        DM, DFF_, 1.f, 1.f, 1.f);
    add_ln_kernel<4, false><<<S_LEN, 128>>>(O1, F, ln2_g, ln2_b, out, (__half*)0);
}

// round 14
// speedup vs baseline: 1.1146x; 1.0986x over previous
#include <cuda_runtime.h>
#include <cuda_bf16.h>
#include <cuda_fp16.h>
#include <math.h>

// ---------------------------------------------------------------------------
// EncoderLayer: x[1,4096,512] -> full transformer encoder layer.
//   fp16 (m16n8k16) tensor-core GEMMs (split-K, fp16 partials) +
//   bf16 flash attention (BQ=128: 32 queries/warp, BKV=64, exp2 softmax).
// ---------------------------------------------------------------------------

#define S_LEN 4096
#define DM    512
#define DFF_  2048
#define NH    8
#define DH    64

// Scratch (device globals: no allocation allowed in kernel_launch)
__device__ __half g_xh [S_LEN * DM];
__device__ __half g_wqh[DM * DM];
__device__ __half g_wkh[DM * DM];
__device__ __half g_wvh[DM * DM];
__device__ __half g_dwh[DM * DM];
__device__ __half g_l1h[DFF_ * DM];
__device__ __half g_l2h[DM * DFF_];
__device__ __nv_bfloat16 g_Qb[S_LEN * DM];
__device__ __nv_bfloat16 g_Kb[S_LEN * DM];
__device__ __nv_bfloat16 g_Vb[S_LEN * DM];
__device__ __half g_CTXh[S_LEN * DM];
__device__ __half g_O1h [S_LEN * DM];
__device__ __half g_Hh  [S_LEN * DFF_];
__device__ __half g_ATT[2 * S_LEN * DM];   // 2 split-K fp16 partials
__device__ float  g_O1 [S_LEN * DM];
__device__ __half g_F  [4 * S_LEN * DM];   // 4 split-K fp16 partials

// ---------------------------------------------------------------------------
// PTX helpers
// ---------------------------------------------------------------------------
__device__ __forceinline__ void mma_bf16(float* c, const unsigned* a,
                                         unsigned b0, unsigned b1) {
    asm volatile(
        "mma.sync.aligned.m16n8k16.row.col.f32.bf16.bf16.f32 "
        "{%0,%1,%2,%3}, {%4,%5,%6,%7}, {%8,%9}, {%0,%1,%2,%3};"
        : "+f"(c[0]), "+f"(c[1]), "+f"(c[2]), "+f"(c[3])
        : "r"(a[0]), "r"(a[1]), "r"(a[2]), "r"(a[3]), "r"(b0), "r"(b1));
}

__device__ __forceinline__ void mma_f16(float* c, const unsigned* a,
                                        unsigned b0, unsigned b1) {
    asm volatile(
        "mma.sync.aligned.m16n8k16.row.col.f32.f16.f16.f32 "
        "{%0,%1,%2,%3}, {%4,%5,%6,%7}, {%8,%9}, {%0,%1,%2,%3};"
        : "+f"(c[0]), "+f"(c[1]), "+f"(c[2]), "+f"(c[3])
        : "r"(a[0]), "r"(a[1]), "r"(a[2]), "r"(a[3]), "r"(b0), "r"(b1));
}

__device__ __forceinline__ void ldsm_x4(unsigned& d0, unsigned& d1,
                                        unsigned& d2, unsigned& d3, unsigned addr) {
    asm volatile("ldmatrix.sync.aligned.m8n8.x4.shared.b16 {%0,%1,%2,%3}, [%4];"
                 : "=r"(d0), "=r"(d1), "=r"(d2), "=r"(d3) : "r"(addr));
}

__device__ __forceinline__ void ldsm_x4_t(unsigned& d0, unsigned& d1,
                                          unsigned& d2, unsigned& d3, unsigned addr) {
    asm volatile("ldmatrix.sync.aligned.m8n8.x4.trans.shared.b16 {%0,%1,%2,%3}, [%4];"
                 : "=r"(d0), "=r"(d1), "=r"(d2), "=r"(d3) : "r"(addr));
}

__device__ __forceinline__ unsigned pack_bf16(float lo, float hi) {
    unsigned r;
    asm("cvt.rn.bf16x2.f32 %0, %1, %2;" : "=r"(r) : "f"(hi), "f"(lo));
    return r;
}

__device__ __forceinline__ unsigned pack_f16(float lo, float hi) {
    unsigned r;
    asm("{\n\t.reg .f16 l, h;\n\tcvt.rn.f16.f32 l, %1;\n\tcvt.rn.f16.f32 h, %2;\n\t"
        "mov.b32 %0, {l, h};\n\t}" : "=r"(r) : "f"(lo), "f"(hi));
    return r;
}

__device__ __forceinline__ float2 unpack_f16(unsigned u) {
    __half2 h = *(__half2*)&u;
    return __half22float2(h);
}

__device__ __forceinline__ float ex2(float x) {
    float r;
    asm("ex2.approx.f32 %0, %1;" : "=f"(r) : "f"(x));
    return r;
}

__device__ __forceinline__ void cp16(unsigned dst, const void* src) {
    asm volatile("cp.async.cg.shared.global [%0], [%1], 16;"
                 :: "r"(dst), "l"(src));
}

// ---------------------------------------------------------------------------
// Merged f32 -> f16 convert: all 7 tensors in ONE launch (5120 blocks).
// ---------------------------------------------------------------------------
__global__ void __launch_bounds__(256)
f2h_all_kernel(const float* __restrict__ x,  __half* __restrict__ xh,
               const float* __restrict__ wq, __half* __restrict__ wqh,
               const float* __restrict__ wk, __half* __restrict__ wkh,
               const float* __restrict__ wv, __half* __restrict__ wvh,
               const float* __restrict__ dw, __half* __restrict__ dwh,
               const float* __restrict__ l1, __half* __restrict__ l1h,
               const float* __restrict__ l2, __half* __restrict__ l2h)
{
    int b = blockIdx.x;
    const float* src; __half* dst; int lb;
    if      (b < 2048) { src = x;  dst = xh;  lb = b; }
    else if (b < 2304) { src = wq; dst = wqh; lb = b - 2048; }
    else if (b < 2560) { src = wk; dst = wkh; lb = b - 2304; }
    else if (b < 2816) { src = wv; dst = wvh; lb = b - 2560; }
    else if (b < 3072) { src = dw; dst = dwh; lb = b - 2816; }
    else if (b < 4096) { src = l1; dst = l1h; lb = b - 3072; }
    else               { src = l2; dst = l2h; lb = b - 4096; }
    int i = (lb * 256 + threadIdx.x) * 4;
    float4 v = *(const float4*)(src + i);
    *(uint2*)(dst + i) = make_uint2(pack_f16(v.x, v.y), pack_f16(v.z, v.w));
}

// ---------------------------------------------------------------------------
// fp16 tensor-core NT GEMM (unchanged from R12).
// ---------------------------------------------------------------------------
#define HSTR 40
#define HTILE (128 * HSTR)   // fp16 units per tile

template<bool RELU, int OUT, int SPLITK>
__global__ void __launch_bounds__(256)
gemm_f16_kernel(const __half* __restrict__ A,
                const __half* __restrict__ W0, const float* __restrict__ bi0, void* __restrict__ C0,
                const __half* __restrict__ W1, const float* __restrict__ bi1, void* __restrict__ C1,
                const __half* __restrict__ W2, const float* __restrict__ bi2, void* __restrict__ C2,
                int N, int K, float s0, float s1, float s2)
{
    __shared__ __half As[2][HTILE];
    __shared__ __half Bs[2][HTILE];

    const __half* B    = W0;
    const float*  bias = bi0;
    void*         Cv   = C0;
    float         scl  = s0;
    int           kslice = 0;
    if (SPLITK > 1) {
        kslice = blockIdx.z;
    } else {
        if (blockIdx.z == 1) { B = W1; bias = bi1; Cv = C1; scl = s1; }
        if (blockIdx.z == 2) { B = W2; bias = bi2; Cv = C2; scl = s2; }
    }
    const int KS = (SPLITK > 1) ? (K / SPLITK) : K;

    const int t    = threadIdx.x;
    const int w    = t >> 5;
    const int lane = t & 31;
    const int grp  = lane >> 2;
    const int tig  = lane & 3;
    const int wm   = w >> 2;
    const int wn   = w & 3;
    const int m0   = blockIdx.y * 128;
    const int n0   = blockIdx.x * 128;
    const int NC   = KS >> 5;

    const __half* Ak = A + (size_t)kslice * KS;
    const __half* Bk = B + (size_t)kslice * KS;
    __half* Cpart = (__half*)Cv;
    if (SPLITK > 1)
        Cpart += (size_t)kslice * (size_t)(gridDim.y * 128) * (size_t)N;

    const int lrow = t >> 1;
    const int lc   = (t & 1) * 2;

    const unsigned aB = (unsigned)__cvta_generic_to_shared(&As[0][0]);
    const unsigned bB = (unsigned)__cvta_generic_to_shared(&Bs[0][0]);

    float acc[4][4][4];
    #pragma unroll
    for (int i = 0; i < 4; ++i)
        #pragma unroll
        for (int j = 0; j < 4; ++j)
            #pragma unroll
            for (int c = 0; c < 4; ++c) acc[i][j][c] = 0.f;

    #define HGLOAD(KT, BUF)                                                     \
        {                                                                       \
            const __half* a = Ak + (size_t)(m0 + lrow) * K + (KT) + lc * 8;     \
            const __half* b = Bk + (size_t)(n0 + lrow) * K + (KT) + lc * 8;     \
            const unsigned ad = aB + (unsigned)(((BUF)*HTILE + lrow*HSTR + lc*8) * 2); \
            const unsigned bd = bB + (unsigned)(((BUF)*HTILE + lrow*HSTR + lc*8) * 2); \
            cp16(ad,       a);                                                  \
            cp16(ad + 16u, a + 8);                                              \
            cp16(bd,       b);                                                  \
            cp16(bd + 16u, b + 8);                                              \
        }

    HGLOAD(0, 0);
    asm volatile("cp.async.commit_group;" ::: "memory");

    for (int it = 0; it < NC; ++it) {
        const int buf = it & 1;
        if (it + 1 < NC) {
            HGLOAD((it + 1) << 5, buf ^ 1);
            asm volatile("cp.async.commit_group;" ::: "memory");
            asm volatile("cp.async.wait_group 1;" ::: "memory");
        } else {
            asm volatile("cp.async.wait_group 0;" ::: "memory");
        }
        __syncthreads();

        const unsigned aS = aB + (unsigned)(buf * HTILE * 2);
        const unsigned bS = bB + (unsigned)(buf * HTILE * 2);

        unsigned bf[4][4];
        #pragma unroll
        for (int j = 0; j < 4; ++j)
            ldsm_x4(bf[j][0], bf[j][1], bf[j][2], bf[j][3],
                    bS + (unsigned)(((wn*32 + j*8 + (lane & 7)) * HSTR
                                     + (lane >> 3) * 8) * 2));

        #pragma unroll
        for (int kc = 0; kc < 2; ++kc) {
            unsigned af[4][4];
            #pragma unroll
            for (int i = 0; i < 4; ++i)
                ldsm_x4(af[i][0], af[i][1], af[i][2], af[i][3],
                        aS + (unsigned)(((wm*64 + i*16 + (lane & 15)) * HSTR
                                         + kc*16 + (lane >> 4) * 8) * 2));
            #pragma unroll
            for (int i = 0; i < 4; ++i)
                #pragma unroll
                for (int j = 0; j < 4; ++j)
                    mma_f16(acc[i][j], af[i], bf[j][2*kc], bf[j][2*kc + 1]);
        }
        __syncthreads();
    }
    #undef HGLOAD

    #pragma unroll
    for (int j = 0; j < 4; ++j) {
        const int col = n0 + wn*32 + j*8 + 2*tig;
        float2 bj = make_float2(0.f, 0.f);
        if (SPLITK == 1 || kslice == 0) bj = *(const float2*)&bias[col];
        #pragma unroll
        for (int i = 0; i < 4; ++i) {
            const int row = m0 + wm*64 + i*16 + grp;
            float2 v0 = make_float2((acc[i][j][0] + bj.x) * scl, (acc[i][j][1] + bj.y) * scl);
            float2 v1 = make_float2((acc[i][j][2] + bj.x) * scl, (acc[i][j][3] + bj.y) * scl);
            if (RELU) {
                v0.x = fmaxf(v0.x, 0.f); v0.y = fmaxf(v0.y, 0.f);
                v1.x = fmaxf(v1.x, 0.f); v1.y = fmaxf(v1.y, 0.f);
            }
            if (OUT == 1) {
                __nv_bfloat16* Cb = (__nv_bfloat16*)Cv;
                *(unsigned*)&Cb[(size_t)row       * N + col] = pack_bf16(v0.x, v0.y);
                *(unsigned*)&Cb[(size_t)(row + 8) * N + col] = pack_bf16(v1.x, v1.y);
            } else if (OUT == 2) {
                __half* Ch = (__half*)Cv;
                *(unsigned*)&Ch[(size_t)row       * N + col] = pack_f16(v0.x, v0.y);
                *(unsigned*)&Ch[(size_t)(row + 8) * N + col] = pack_f16(v1.x, v1.y);
            } else {
                *(unsigned*)&Cpart[(size_t)row       * N + col] = pack_f16(v0.x, v0.y);
                *(unsigned*)&Cpart[(size_t)(row + 8) * N + col] = pack_f16(v1.x, v1.y);
            }
        }
    }
}

// ---------------------------------------------------------------------------
// bf16 flash attention, BQ=128: 4 warps x 32 queries (2 m16 frags per warp).
// Each K/V ldmatrix feeds 4 MMAs (was 2) -> smem read per FLOP halved.
// BKV=64, exp2-domain softmax. Dynamic smem 55296 B.
// ---------------------------------------------------------------------------
#define BQ    128
#define BKV   64
#define NTT   (S_LEN / BKV)   // 64
#define KSTRb 72              // bf16 units; 144B row stride
#define PSTRb 72

__global__ void __launch_bounds__(128)
flash_attn_bf16_kernel(const __nv_bfloat16* __restrict__ Q,
                       const __nv_bfloat16* __restrict__ K,
                       const __nv_bfloat16* __restrict__ V,
                       __half* __restrict__ O)
{
    extern __shared__ __nv_bfloat16 smem[];
    // layout (bf16 units): Ks[2][BKV*KSTRb] | Vs[2][BKV*KSTRb] | Ps[BQ*PSTRb]
    const unsigned sB     = (unsigned)__cvta_generic_to_shared(smem);
    const unsigned ksBase = sB;
    const unsigned vsBase = sB + (unsigned)(2 * BKV * KSTRb * 2);
    __nv_bfloat16* Ps     = smem + 4 * BKV * KSTRb;

    const int t    = threadIdx.x;
    const int w    = t >> 5;      // 0..3, warp owns rows w*32..w*32+31
    const int lane = t & 31;
    const int grp  = lane >> 2;
    const int tig  = lane & 3;
    const int h    = blockIdx.y;
    const int q0   = blockIdx.x * BQ;

    // Q fragments for both 16-row groups (pre-scaled at QKV epilogue)
    unsigned qa[2][4][4];
    #pragma unroll
    for (int mq = 0; mq < 2; ++mq) {
        const __nv_bfloat16* Qb = Q + (size_t)(q0 + w*32 + mq*16) * DM + h * DH;
        #pragma unroll
        for (int kc = 0; kc < 4; ++kc) {
            qa[mq][kc][0] = *(const unsigned*)&Qb[(size_t)grp       * DM + kc*16 + 2*tig];
            qa[mq][kc][1] = *(const unsigned*)&Qb[(size_t)(grp + 8) * DM + kc*16 + 2*tig];
            qa[mq][kc][2] = *(const unsigned*)&Qb[(size_t)grp       * DM + kc*16 + 8 + 2*tig];
            qa[mq][kc][3] = *(const unsigned*)&Qb[(size_t)(grp + 8) * DM + kc*16 + 8 + 2*tig];
        }
    }

    float of[2][8][4];
    #pragma unroll
    for (int mq = 0; mq < 2; ++mq)
        #pragma unroll
        for (int n = 0; n < 8; ++n)
            #pragma unroll
            for (int c = 0; c < 4; ++c) of[mq][n][c] = 0.f;

    float mM[2][2] = {{-1e30f, -1e30f}, {-1e30f, -1e30f}};
    float lL[2][2] = {{0.f, 0.f}, {0.f, 0.f}};

    // K/V tile loader: 64 rows x 128B each, 128 threads x 4 row-passes
    const int lr = t >> 3;
    const int c8 = t & 7;

    #define LOAD_TILE(KB, B)                                                          \
        {                                                                             \
            const size_t krow = (size_t)((KB) * BKV);                                 \
            _Pragma("unroll")                                                         \
            for (int i = 0; i < 4; ++i) {                                             \
                const int r = lr + 16 * i;                                            \
                cp16(ksBase + (unsigned)((((B)*BKV + r)*KSTRb + c8*8) * 2),           \
                     K + (krow + r) * DM + h * DH + c8 * 8);                          \
                cp16(vsBase + (unsigned)((((B)*BKV + r)*KSTRb + c8*8) * 2),           \
                     V + (krow + r) * DM + h * DH + c8 * 8);                          \
            }                                                                         \
        }

    LOAD_TILE(0, 0);
    asm volatile("cp.async.commit_group;" ::: "memory");

    for (int kb = 0; kb < NTT; ++kb) {
        const int buf = kb & 1;
        if (kb + 1 < NTT) {
            LOAD_TILE(kb + 1, buf ^ 1);
            asm volatile("cp.async.commit_group;" ::: "memory");
            asm volatile("cp.async.wait_group 1;" ::: "memory");
        } else {
            asm volatile("cp.async.wait_group 0;" ::: "memory");
        }
        __syncthreads();

        const unsigned kbuf = ksBase + (unsigned)(buf * BKV * KSTRb * 2);
        const unsigned vbuf = vsBase + (unsigned)(buf * BKV * KSTRb * 2);

        // ---- S = Qs K^T : 32x64 per warp; each ldsm feeds 4 MMAs ----
        float sf[2][8][4];
        #pragma unroll
        for (int mq = 0; mq < 2; ++mq)
            #pragma unroll
            for (int n = 0; n < 8; ++n)
                sf[mq][n][0] = sf[mq][n][1] = sf[mq][n][2] = sf[mq][n][3] = 0.f;

        #pragma unroll
        for (int kcp = 0; kcp < 2; ++kcp) {
            #pragma unroll
            for (int n = 0; n < 8; ++n) {
                unsigned d0, d1, d2, d3;
                const unsigned addr = kbuf +
                    (unsigned)(((n*8 + (lane & 7)) * KSTRb + kcp*32 + (lane >> 3) * 8) * 2);
                ldsm_x4(d0, d1, d2, d3, addr);
                mma_bf16(sf[0][n], qa[0][2*kcp],     d0, d1);
                mma_bf16(sf[0][n], qa[0][2*kcp + 1], d2, d3);
                mma_bf16(sf[1][n], qa[1][2*kcp],     d0, d1);
                mma_bf16(sf[1][n], qa[1][2*kcp + 1], d2, d3);
            }
        }

        // ---- online softmax (log2 domain), per 16-row group ----
        #pragma unroll
        for (int mq = 0; mq < 2; ++mq) {
            float mx0 = -1e30f, mx1 = -1e30f;
            #pragma unroll
            for (int n = 0; n < 8; ++n) {
                mx0 = fmaxf(mx0, fmaxf(sf[mq][n][0], sf[mq][n][1]));
                mx1 = fmaxf(mx1, fmaxf(sf[mq][n][2], sf[mq][n][3]));
            }
            mx0 = fmaxf(mx0, __shfl_xor_sync(0xffffffffu, mx0, 1));
            mx0 = fmaxf(mx0, __shfl_xor_sync(0xffffffffu, mx0, 2));
            mx1 = fmaxf(mx1, __shfl_xor_sync(0xffffffffu, mx1, 1));
            mx1 = fmaxf(mx1, __shfl_xor_sync(0xffffffffu, mx1, 2));

            const float mn0 = fmaxf(mM[mq][0], mx0);
            const float mn1 = fmaxf(mM[mq][1], mx1);
            const float al0 = ex2(mM[mq][0] - mn0);
            const float al1 = ex2(mM[mq][1] - mn1);

            float s0 = 0.f, s1 = 0.f;
            #pragma unroll
            for (int n = 0; n < 8; ++n) {
                sf[mq][n][0] = ex2(sf[mq][n][0] - mn0); s0 += sf[mq][n][0];
                sf[mq][n][1] = ex2(sf[mq][n][1] - mn0); s0 += sf[mq][n][1];
                sf[mq][n][2] = ex2(sf[mq][n][2] - mn1); s1 += sf[mq][n][2];
                sf[mq][n][3] = ex2(sf[mq][n][3] - mn1); s1 += sf[mq][n][3];
            }
            s0 += __shfl_xor_sync(0xffffffffu, s0, 1);
            s0 += __shfl_xor_sync(0xffffffffu, s0, 2);
            s1 += __shfl_xor_sync(0xffffffffu, s1, 1);
            s1 += __shfl_xor_sync(0xffffffffu, s1, 2);

            lL[mq][0] = lL[mq][0] * al0 + s0;  mM[mq][0] = mn0;
            lL[mq][1] = lL[mq][1] * al1 + s1;  mM[mq][1] = mn1;

            #pragma unroll
            for (int n = 0; n < 8; ++n) {
                of[mq][n][0] *= al0; of[mq][n][1] *= al0;
                of[mq][n][2] *= al1; of[mq][n][3] *= al1;
            }

            // store P rows for this group
            __nv_bfloat16* pr = &Ps[(w*32 + mq*16 + grp) * PSTRb];
            #pragma unroll
            for (int n = 0; n < 8; ++n) {
                *(unsigned*)&pr[n*8 + 2*tig]           = pack_bf16(sf[mq][n][0], sf[mq][n][1]);
                *(unsigned*)&pr[8*PSTRb + n*8 + 2*tig] = pack_bf16(sf[mq][n][2], sf[mq][n][3]);
            }
        }
        __syncwarp();

        // ---- P A-fragments (both groups, 4 k16 chunks over 64 keys) ----
        unsigned pa[2][4][4];
        #pragma unroll
        for (int mq = 0; mq < 2; ++mq) {
            const __nv_bfloat16* pr = &Ps[(w*32 + mq*16 + grp) * PSTRb];
            #pragma unroll
            for (int kc = 0; kc < 4; ++kc) {
                pa[mq][kc][0] = *(const unsigned*)&pr[kc*16 + 2*tig];
                pa[mq][kc][1] = *(const unsigned*)&pr[8*PSTRb + kc*16 + 2*tig];
                pa[mq][kc][2] = *(const unsigned*)&pr[kc*16 + 8 + 2*tig];
                pa[mq][kc][3] = *(const unsigned*)&pr[8*PSTRb + kc*16 + 8 + 2*tig];
            }
        }

        // ---- PV: O(32x64) += P(32x64) V(64x64); each ldsm_t feeds 4 MMAs ----
        #pragma unroll
        for (int kc = 0; kc < 4; ++kc) {
            #pragma unroll
            for (int np = 0; np < 4; ++np) {
                unsigned d0, d1, d2, d3;
                const unsigned addr = vbuf + (unsigned)(
                    ((kc*16 + ((lane >> 3) & 1) * 8 + (lane & 7)) * KSTRb
                     + np*16 + (lane >> 4) * 8) * 2);
                ldsm_x4_t(d0, d1, d2, d3, addr);
                mma_bf16(of[0][2*np],     pa[0][kc], d0, d1);
                mma_bf16(of[0][2*np + 1], pa[0][kc], d2, d3);
                mma_bf16(of[1][2*np],     pa[1][kc], d0, d1);
                mma_bf16(of[1][2*np + 1], pa[1][kc], d2, d3);
            }
        }
        __syncthreads();
    }

    // ---- epilogue ----
    #pragma unroll
    for (int mq = 0; mq < 2; ++mq) {
        const float inv0 = 1.f / lL[mq][0];
        const float inv1 = 1.f / lL[mq][1];
        __half* ob = O + (size_t)(q0 + w*32 + mq*16 + grp) * DM + h * DH;
        #pragma unroll
        for (int n = 0; n < 8; ++n) {
            *(unsigned*)&ob[n*8 + 2*tig] =
                pack_f16(of[mq][n][0] * inv0, of[mq][n][1] * inv0);
            *(unsigned*)&ob[(size_t)8 * DM + n*8 + 2*tig] =
                pack_f16(of[mq][n][2] * inv1, of[mq][n][3] * inv1);
        }
    }
}

#define ATTN_SMEM ((4 * BKV * KSTRb + BQ * PSTRb) * 2)   // 55296 B

// ---------------------------------------------------------------------------
// out = LayerNorm(A + sum of NB fp16 partials of B) * gamma + beta.
// ---------------------------------------------------------------------------
template<int NB, bool DUAL>
__global__ void __launch_bounds__(128)
add_ln_kernel(const float* __restrict__ A, const __half* __restrict__ B,
              const float* __restrict__ gamma, const float* __restrict__ beta,
              float* __restrict__ O, __half* __restrict__ Oh)
{
    __shared__ float red[4];
    const int row = blockIdx.x;
    const int t   = threadIdx.x;
    const int wid = t >> 5;
    const int lane = t & 31;

    const size_t base = (size_t)row * DM + t * 4;
    float4 v = *(const float4*)(A + base);
    #pragma unroll
    for (int p = 0; p < NB; ++p) {
        uint2 bu = *(const uint2*)(B + (size_t)p * S_LEN * DM + base);
        float2 b0 = unpack_f16(bu.x);
        float2 b1 = unpack_f16(bu.y);
        v.x += b0.x; v.y += b0.y; v.z += b1.x; v.w += b1.y;
    }

    float s = v.x + v.y + v.z + v.w;
    #pragma unroll
    for (int o = 16; o > 0; o >>= 1) s += __shfl_xor_sync(0xffffffffu, s, o);
    if (lane == 0) red[wid] = s;
    __syncthreads();
    const float mu = (red[0] + red[1] + red[2] + red[3]) * (1.f / DM);

    float4 d = make_float4(v.x - mu, v.y - mu, v.z - mu, v.w - mu);
    float ss = d.x*d.x + d.y*d.y + d.z*d.z + d.w*d.w;
    #pragma unroll
    for (int o = 16; o > 0; o >>= 1) ss += __shfl_xor_sync(0xffffffffu, ss, o);
    __syncthreads();
    if (lane == 0) red[wid] = ss;
    __syncthreads();
    const float var  = (red[0] + red[1] + red[2] + red[3]) * (1.f / DM);
    const float rstd = rsqrtf(var + 1e-6f);

    float4 g  = *(const float4*)(gamma + t * 4);
    float4 be = *(const float4*)(beta  + t * 4);
    float4 o;
    o.x = d.x * rstd * g.x + be.x;
    o.y = d.y * rstd * g.y + be.y;
    o.z = d.z * rstd * g.z + be.z;
    o.w = d.w * rstd * g.w + be.w;
    *(float4*)(O + base) = o;
    if (DUAL) {
        unsigned lo = pack_f16(o.x, o.y);
        unsigned hi = pack_f16(o.z, o.w);
        *(uint2*)(Oh + base) = make_uint2(lo, hi);
    }
}

// ---------------------------------------------------------------------------
// kernel_launch
// ---------------------------------------------------------------------------
extern "C" void kernel_launch(void* const* d_in, const int* in_sizes, int n_in,
                              void* d_out, int out_size)
{
    const float* x       = (const float*)d_in[0];
    const float* wq_w    = (const float*)d_in[1];
    const float* wq_b    = (const float*)d_in[2];
    const float* wk_w    = (const float*)d_in[3];
    const float* wk_b    = (const float*)d_in[4];
    const float* wv_w    = (const float*)d_in[5];
    const float* wv_b    = (const float*)d_in[6];
    const float* dense_w = (const float*)d_in[7];
    const float* dense_b = (const float*)d_in[8];
    const float* l1_w    = (const float*)d_in[9];
    const float* l1_b    = (const float*)d_in[10];
    const float* l2_w    = (const float*)d_in[11];
    const float* l2_b    = (const float*)d_in[12];
    const float* ln1_g   = (const float*)d_in[13];
    const float* ln1_b   = (const float*)d_in[14];
    const float* ln2_g   = (const float*)d_in[15];
    const float* ln2_b   = (const float*)d_in[16];
    float* out = (float*)d_out;

    __half *xh, *wqh, *wkh, *wvh, *dwh, *l1h, *l2h, *CTXh, *O1h, *Hh, *ATT, *F;
    __nv_bfloat16 *Qb, *Kb, *Vb;
    float *O1;
    cudaGetSymbolAddress((void**)&xh,   g_xh);
    cudaGetSymbolAddress((void**)&wqh,  g_wqh);
    cudaGetSymbolAddress((void**)&wkh,  g_wkh);
    cudaGetSymbolAddress((void**)&wvh,  g_wvh);
    cudaGetSymbolAddress((void**)&dwh,  g_dwh);
    cudaGetSymbolAddress((void**)&l1h,  g_l1h);
    cudaGetSymbolAddress((void**)&l2h,  g_l2h);
    cudaGetSymbolAddress((void**)&Qb,   g_Qb);
    cudaGetSymbolAddress((void**)&Kb,   g_Kb);
    cudaGetSymbolAddress((void**)&Vb,   g_Vb);
    cudaGetSymbolAddress((void**)&CTXh, g_CTXh);
    cudaGetSymbolAddress((void**)&O1h,  g_O1h);
    cudaGetSymbolAddress((void**)&Hh,   g_Hh);
    cudaGetSymbolAddress((void**)&ATT,  g_ATT);
    cudaGetSymbolAddress((void**)&O1,   g_O1);
    cudaGetSymbolAddress((void**)&F,    g_F);

    // attention needs 54 KB dynamic smem (idempotent host-side call)
    cudaFuncSetAttribute(flash_attn_bf16_kernel,
                         cudaFuncAttributeMaxDynamicSharedMemorySize, ATTN_SMEM);

    // fp32 -> fp16 conversions, single merged launch
    f2h_all_kernel<<<5120, 256>>>(x, xh, wq_w, wqh, wk_w, wkh, wv_w, wvh,
                                  dense_w, dwh, l1_w, l1h, l2_w, l2h);

    // QKV projections, batched. Q scale = (1/sqrt(64)) * log2(e) for exp2 softmax.
    gemm_f16_kernel<false, 1, 1><<<dim3(DM/128, S_LEN/128, 3), 256>>>(
        xh,
        wqh, wq_b, Qb,
        wkh, wk_b, Kb,
        wvh, wv_b, Vb,
        DM, DM, 0.125f * 1.44269504088896f, 1.f, 1.f);

    // attention (BQ=128: 256 CTAs; fp16 CTX out)
    flash_attn_bf16_kernel<<<dim3(S_LEN / BQ, NH), 128, ATTN_SMEM>>>(
        Qb, Kb, Vb, CTXh);

    // dense proj: split-K=2, fp16 partials + fused-reduce LN
    gemm_f16_kernel<false, 0, 2><<<dim3(DM/128, S_LEN/128, 2), 256>>>(
        CTXh,
        dwh, dense_b, ATT,
        dwh, dense_b, ATT,
        dwh, dense_b, ATT,
        DM, DM, 1.f, 1.f, 1.f);
    add_ln_kernel<2, true><<<S_LEN, 128>>>(x, ATT, ln1_g, ln1_b, O1, O1h);

    // FFN1 (grid 512, H fp16)
    gemm_f16_kernel<true, 2, 1><<<dim3(DFF_/128, S_LEN/128, 1), 256>>>(
        O1h,
        l1h, l1_b, Hh,
        l1h, l1_b, Hh,
        l1h, l1_b, Hh,
        DFF_, DM, 1.f, 1.f, 1.f);

    // FFN2: split-K=4, fp16 partials + fused-reduce LN
    gemm_f16_kernel<false, 0, 4><<<dim3(DM/128, S_LEN/128, 4), 256>>>(
        Hh,
        l2h, l2_b, F,
        l2h, l2_b, F,
        l2h, l2_b, F,
        DM, DFF_, 1.f, 1.f, 1.f);
    add_ln_kernel<4, false><<<S_LEN, 128>>>(O1, F, ln2_g, ln2_b, out, (__half*)0);
}

// round 15
// speedup vs baseline: 1.1610x; 1.0417x over previous
#include <cuda_runtime.h>
#include <cuda_bf16.h>
#include <cuda_fp16.h>
#include <math.h>

// ---------------------------------------------------------------------------
// EncoderLayer: x[1,4096,512] -> full transformer encoder layer.
//   fp16 (m16n8k16) tensor-core GEMMs (split-K, fp16 partials) +
//   bf16 flash attention (BQ=128, BKV=64, exp2 softmax,
//   register-direct P re-fragmentation: no smem round-trip).
// ---------------------------------------------------------------------------

#define S_LEN 4096
#define DM    512
#define DFF_  2048
#define NH    8
#define DH    64

// Scratch (device globals: no allocation allowed in kernel_launch)
__device__ __half g_xh [S_LEN * DM];
__device__ __half g_wqh[DM * DM];
__device__ __half g_wkh[DM * DM];
__device__ __half g_wvh[DM * DM];
__device__ __half g_dwh[DM * DM];
__device__ __half g_l1h[DFF_ * DM];
__device__ __half g_l2h[DM * DFF_];
__device__ __nv_bfloat16 g_Qb[S_LEN * DM];
__device__ __nv_bfloat16 g_Kb[S_LEN * DM];
__device__ __nv_bfloat16 g_Vb[S_LEN * DM];
__device__ __half g_CTXh[S_LEN * DM];
__device__ __half g_O1h [S_LEN * DM];
__device__ __half g_Hh  [S_LEN * DFF_];
__device__ __half g_ATT[2 * S_LEN * DM];   // 2 split-K fp16 partials
__device__ float  g_O1 [S_LEN * DM];
__device__ __half g_F  [4 * S_LEN * DM];   // 4 split-K fp16 partials

// ---------------------------------------------------------------------------
// PTX helpers
// ---------------------------------------------------------------------------
__device__ __forceinline__ void mma_bf16(float* c, const unsigned* a,
                                         unsigned b0, unsigned b1) {
    asm volatile(
        "mma.sync.aligned.m16n8k16.row.col.f32.bf16.bf16.f32 "
        "{%0,%1,%2,%3}, {%4,%5,%6,%7}, {%8,%9}, {%0,%1,%2,%3};"
        : "+f"(c[0]), "+f"(c[1]), "+f"(c[2]), "+f"(c[3])
        : "r"(a[0]), "r"(a[1]), "r"(a[2]), "r"(a[3]), "r"(b0), "r"(b1));
}

__device__ __forceinline__ void mma_f16(float* c, const unsigned* a,
                                        unsigned b0, unsigned b1) {
    asm volatile(
        "mma.sync.aligned.m16n8k16.row.col.f32.f16.f16.f32 "
        "{%0,%1,%2,%3}, {%4,%5,%6,%7}, {%8,%9}, {%0,%1,%2,%3};"
        : "+f"(c[0]), "+f"(c[1]), "+f"(c[2]), "+f"(c[3])
        : "r"(a[0]), "r"(a[1]), "r"(a[2]), "r"(a[3]), "r"(b0), "r"(b1));
}

__device__ __forceinline__ void ldsm_x4(unsigned& d0, unsigned& d1,
                                        unsigned& d2, unsigned& d3, unsigned addr) {
    asm volatile("ldmatrix.sync.aligned.m8n8.x4.shared.b16 {%0,%1,%2,%3}, [%4];"
                 : "=r"(d0), "=r"(d1), "=r"(d2), "=r"(d3) : "r"(addr));
}

__device__ __forceinline__ void ldsm_x4_t(unsigned& d0, unsigned& d1,
                                          unsigned& d2, unsigned& d3, unsigned addr) {
    asm volatile("ldmatrix.sync.aligned.m8n8.x4.trans.shared.b16 {%0,%1,%2,%3}, [%4];"
                 : "=r"(d0), "=r"(d1), "=r"(d2), "=r"(d3) : "r"(addr));
}

__device__ __forceinline__ unsigned pack_bf16(float lo, float hi) {
    unsigned r;
    asm("cvt.rn.bf16x2.f32 %0, %1, %2;" : "=r"(r) : "f"(hi), "f"(lo));
    return r;
}

__device__ __forceinline__ unsigned pack_f16(float lo, float hi) {
    unsigned r;
    asm("{\n\t.reg .f16 l, h;\n\tcvt.rn.f16.f32 l, %1;\n\tcvt.rn.f16.f32 h, %2;\n\t"
        "mov.b32 %0, {l, h};\n\t}" : "=r"(r) : "f"(lo), "f"(hi));
    return r;
}

__device__ __forceinline__ float2 unpack_f16(unsigned u) {
    __half2 h = *(__half2*)&u;
    return __half22float2(h);
}

__device__ __forceinline__ float ex2(float x) {
    float r;
    asm("ex2.approx.f32 %0, %1;" : "=f"(r) : "f"(x));
    return r;
}

__device__ __forceinline__ void cp16(unsigned dst, const void* src) {
    asm volatile("cp.async.cg.shared.global [%0], [%1], 16;"
                 :: "r"(dst), "l"(src));
}

// ---------------------------------------------------------------------------
// Merged f32 -> f16 convert: all 7 tensors in ONE launch (5120 blocks).
// ---------------------------------------------------------------------------
__global__ void __launch_bounds__(256)
f2h_all_kernel(const float* __restrict__ x,  __half* __restrict__ xh,
               const float* __restrict__ wq, __half* __restrict__ wqh,
               const float* __restrict__ wk, __half* __restrict__ wkh,
               const float* __restrict__ wv, __half* __restrict__ wvh,
               const float* __restrict__ dw, __half* __restrict__ dwh,
               const float* __restrict__ l1, __half* __restrict__ l1h,
               const float* __restrict__ l2, __half* __restrict__ l2h)
{
    int b = blockIdx.x;
    const float* src; __half* dst; int lb;
    if      (b < 2048) { src = x;  dst = xh;  lb = b; }
    else if (b < 2304) { src = wq; dst = wqh; lb = b - 2048; }
    else if (b < 2560) { src = wk; dst = wkh; lb = b - 2304; }
    else if (b < 2816) { src = wv; dst = wvh; lb = b - 2560; }
    else if (b < 3072) { src = dw; dst = dwh; lb = b - 2816; }
    else if (b < 4096) { src = l1; dst = l1h; lb = b - 3072; }
    else               { src = l2; dst = l2h; lb = b - 4096; }
    int i = (lb * 256 + threadIdx.x) * 4;
    float4 v = *(const float4*)(src + i);
    *(uint2*)(dst + i) = make_uint2(pack_f16(v.x, v.y), pack_f16(v.z, v.w));
}

// ---------------------------------------------------------------------------
// fp16 tensor-core NT GEMM (unchanged from R12).
// ---------------------------------------------------------------------------
#define HSTR 40
#define HTILE (128 * HSTR)   // fp16 units per tile

template<bool RELU, int OUT, int SPLITK>
__global__ void __launch_bounds__(256)
gemm_f16_kernel(const __half* __restrict__ A,
                const __half* __restrict__ W0, const float* __restrict__ bi0, void* __restrict__ C0,
                const __half* __restrict__ W1, const float* __restrict__ bi1, void* __restrict__ C1,
                const __half* __restrict__ W2, const float* __restrict__ bi2, void* __restrict__ C2,
                int N, int K, float s0, float s1, float s2)
{
    __shared__ __half As[2][HTILE];
    __shared__ __half Bs[2][HTILE];

    const __half* B    = W0;
    const float*  bias = bi0;
    void*         Cv   = C0;
    float         scl  = s0;
    int           kslice = 0;
    if (SPLITK > 1) {
        kslice = blockIdx.z;
    } else {
        if (blockIdx.z == 1) { B = W1; bias = bi1; Cv = C1; scl = s1; }
        if (blockIdx.z == 2) { B = W2; bias = bi2; Cv = C2; scl = s2; }
    }
    const int KS = (SPLITK > 1) ? (K / SPLITK) : K;

    const int t    = threadIdx.x;
    const int w    = t >> 5;
    const int lane = t & 31;
    const int grp  = lane >> 2;
    const int tig  = lane & 3;
    const int wm   = w >> 2;
    const int wn   = w & 3;
    const int m0   = blockIdx.y * 128;
    const int n0   = blockIdx.x * 128;
    const int NC   = KS >> 5;

    const __half* Ak = A + (size_t)kslice * KS;
    const __half* Bk = B + (size_t)kslice * KS;
    __half* Cpart = (__half*)Cv;
    if (SPLITK > 1)
        Cpart += (size_t)kslice * (size_t)(gridDim.y * 128) * (size_t)N;

    const int lrow = t >> 1;
    const int lc   = (t & 1) * 2;

    const unsigned aB = (unsigned)__cvta_generic_to_shared(&As[0][0]);
    const unsigned bB = (unsigned)__cvta_generic_to_shared(&Bs[0][0]);

    float acc[4][4][4];
    #pragma unroll
    for (int i = 0; i < 4; ++i)
        #pragma unroll
        for (int j = 0; j < 4; ++j)
            #pragma unroll
            for (int c = 0; c < 4; ++c) acc[i][j][c] = 0.f;

    #define HGLOAD(KT, BUF)                                                     \
        {                                                                       \
            const __half* a = Ak + (size_t)(m0 + lrow) * K + (KT) + lc * 8;     \
            const __half* b = Bk + (size_t)(n0 + lrow) * K + (KT) + lc * 8;     \
            const unsigned ad = aB + (unsigned)(((BUF)*HTILE + lrow*HSTR + lc*8) * 2); \
            const unsigned bd = bB + (unsigned)(((BUF)*HTILE + lrow*HSTR + lc*8) * 2); \
            cp16(ad,       a);                                                  \
            cp16(ad + 16u, a + 8);                                              \
            cp16(bd,       b);                                                  \
            cp16(bd + 16u, b + 8);                                              \
        }

    HGLOAD(0, 0);
    asm volatile("cp.async.commit_group;" ::: "memory");

    for (int it = 0; it < NC; ++it) {
        const int buf = it & 1;
        if (it + 1 < NC) {
            HGLOAD((it + 1) << 5, buf ^ 1);
            asm volatile("cp.async.commit_group;" ::: "memory");
            asm volatile("cp.async.wait_group 1;" ::: "memory");
        } else {
            asm volatile("cp.async.wait_group 0;" ::: "memory");
        }
        __syncthreads();

        const unsigned aS = aB + (unsigned)(buf * HTILE * 2);
        const unsigned bS = bB + (unsigned)(buf * HTILE * 2);

        unsigned bf[4][4];
        #pragma unroll
        for (int j = 0; j < 4; ++j)
            ldsm_x4(bf[j][0], bf[j][1], bf[j][2], bf[j][3],
                    bS + (unsigned)(((wn*32 + j*8 + (lane & 7)) * HSTR
                                     + (lane >> 3) * 8) * 2));

        #pragma unroll
        for (int kc = 0; kc < 2; ++kc) {
            unsigned af[4][4];
            #pragma unroll
            for (int i = 0; i < 4; ++i)
                ldsm_x4(af[i][0], af[i][1], af[i][2], af[i][3],
                        aS + (unsigned)(((wm*64 + i*16 + (lane & 15)) * HSTR
                                         + kc*16 + (lane >> 4) * 8) * 2));
            #pragma unroll
            for (int i = 0; i < 4; ++i)
                #pragma unroll
                for (int j = 0; j < 4; ++j)
                    mma_f16(acc[i][j], af[i], bf[j][2*kc], bf[j][2*kc + 1]);
        }
        __syncthreads();
    }
    #undef HGLOAD

    #pragma unroll
    for (int j = 0; j < 4; ++j) {
        const int col = n0 + wn*32 + j*8 + 2*tig;
        float2 bj = make_float2(0.f, 0.f);
        if (SPLITK == 1 || kslice == 0) bj = *(const float2*)&bias[col];
        #pragma unroll
        for (int i = 0; i < 4; ++i) {
            const int row = m0 + wm*64 + i*16 + grp;
            float2 v0 = make_float2((acc[i][j][0] + bj.x) * scl, (acc[i][j][1] + bj.y) * scl);
            float2 v1 = make_float2((acc[i][j][2] + bj.x) * scl, (acc[i][j][3] + bj.y) * scl);
            if (RELU) {
                v0.x = fmaxf(v0.x, 0.f); v0.y = fmaxf(v0.y, 0.f);
                v1.x = fmaxf(v1.x, 0.f); v1.y = fmaxf(v1.y, 0.f);
            }
            if (OUT == 1) {
                __nv_bfloat16* Cb = (__nv_bfloat16*)Cv;
                *(unsigned*)&Cb[(size_t)row       * N + col] = pack_bf16(v0.x, v0.y);
                *(unsigned*)&Cb[(size_t)(row + 8) * N + col] = pack_bf16(v1.x, v1.y);
            } else if (OUT == 2) {
                __half* Ch = (__half*)Cv;
                *(unsigned*)&Ch[(size_t)row       * N + col] = pack_f16(v0.x, v0.y);
                *(unsigned*)&Ch[(size_t)(row + 8) * N + col] = pack_f16(v1.x, v1.y);
            } else {
                *(unsigned*)&Cpart[(size_t)row       * N + col] = pack_f16(v0.x, v0.y);
                *(unsigned*)&Cpart[(size_t)(row + 8) * N + col] = pack_f16(v1.x, v1.y);
            }
        }
    }
}

// ---------------------------------------------------------------------------
// bf16 flash attention, BQ=128, BKV=64, exp2 softmax.
// P re-fragmentation is REGISTER-DIRECT: the S C-fragment layout equals the
// PV A-fragment layout (pa[kc] = packed cols of S-tiles {2kc, 2kc+1}), so
// the P smem round-trip is eliminated entirely. Dynamic smem 36864 B.
// ---------------------------------------------------------------------------
#define BQ    128
#define BKV   64
#define NTT   (S_LEN / BKV)   // 64
#define KSTRb 72              // bf16 units; 144B row stride

__global__ void __launch_bounds__(128)
flash_attn_bf16_kernel(const __nv_bfloat16* __restrict__ Q,
                       const __nv_bfloat16* __restrict__ K,
                       const __nv_bfloat16* __restrict__ V,
                       __half* __restrict__ O)
{
    extern __shared__ __nv_bfloat16 smem[];
    // layout (bf16 units): Ks[2][BKV*KSTRb] | Vs[2][BKV*KSTRb]
    const unsigned sB     = (unsigned)__cvta_generic_to_shared(smem);
    const unsigned ksBase = sB;
    const unsigned vsBase = sB + (unsigned)(2 * BKV * KSTRb * 2);

    const int t    = threadIdx.x;
    const int w    = t >> 5;      // 0..3, warp owns rows w*32..w*32+31
    const int lane = t & 31;
    const int grp  = lane >> 2;
    const int tig  = lane & 3;
    const int h    = blockIdx.y;
    const int q0   = blockIdx.x * BQ;

    // Q fragments for both 16-row groups (pre-scaled at QKV epilogue)
    unsigned qa[2][4][4];
    #pragma unroll
    for (int mq = 0; mq < 2; ++mq) {
        const __nv_bfloat16* Qb = Q + (size_t)(q0 + w*32 + mq*16) * DM + h * DH;
        #pragma unroll
        for (int kc = 0; kc < 4; ++kc) {
            qa[mq][kc][0] = *(const unsigned*)&Qb[(size_t)grp       * DM + kc*16 + 2*tig];
            qa[mq][kc][1] = *(const unsigned*)&Qb[(size_t)(grp + 8) * DM + kc*16 + 2*tig];
            qa[mq][kc][2] = *(const unsigned*)&Qb[(size_t)grp       * DM + kc*16 + 8 + 2*tig];
            qa[mq][kc][3] = *(const unsigned*)&Qb[(size_t)(grp + 8) * DM + kc*16 + 8 + 2*tig];
        }
    }

    float of[2][8][4];
    #pragma unroll
    for (int mq = 0; mq < 2; ++mq)
        #pragma unroll
        for (int n = 0; n < 8; ++n)
            #pragma unroll
            for (int c = 0; c < 4; ++c) of[mq][n][c] = 0.f;

    float mM[2][2] = {{-1e30f, -1e30f}, {-1e30f, -1e30f}};
    float lL[2][2] = {{0.f, 0.f}, {0.f, 0.f}};

    // K/V tile loader: 64 rows x 128B each, 128 threads x 4 row-passes
    const int lr = t >> 3;
    const int c8 = t & 7;

    #define LOAD_TILE(KB, B)                                                          \
        {                                                                             \
            const size_t krow = (size_t)((KB) * BKV);                                 \
            _Pragma("unroll")                                                         \
            for (int i = 0; i < 4; ++i) {                                             \
                const int r = lr + 16 * i;                                            \
                cp16(ksBase + (unsigned)((((B)*BKV + r)*KSTRb + c8*8) * 2),           \
                     K + (krow + r) * DM + h * DH + c8 * 8);                          \
                cp16(vsBase + (unsigned)((((B)*BKV + r)*KSTRb + c8*8) * 2),           \
                     V + (krow + r) * DM + h * DH + c8 * 8);                          \
            }                                                                         \
        }

    LOAD_TILE(0, 0);
    asm volatile("cp.async.commit_group;" ::: "memory");

    for (int kb = 0; kb < NTT; ++kb) {
        const int buf = kb & 1;
        if (kb + 1 < NTT) {
            LOAD_TILE(kb + 1, buf ^ 1);
            asm volatile("cp.async.commit_group;" ::: "memory");
            asm volatile("cp.async.wait_group 1;" ::: "memory");
        } else {
            asm volatile("cp.async.wait_group 0;" ::: "memory");
        }
        __syncthreads();

        const unsigned kbuf = ksBase + (unsigned)(buf * BKV * KSTRb * 2);
        const unsigned vbuf = vsBase + (unsigned)(buf * BKV * KSTRb * 2);

        // ---- S = Qs K^T : 32x64 per warp; each ldsm feeds 4 MMAs ----
        float sf[2][8][4];
        #pragma unroll
        for (int mq = 0; mq < 2; ++mq)
            #pragma unroll
            for (int n = 0; n < 8; ++n)
                sf[mq][n][0] = sf[mq][n][1] = sf[mq][n][2] = sf[mq][n][3] = 0.f;

        #pragma unroll
        for (int kcp = 0; kcp < 2; ++kcp) {
            #pragma unroll
            for (int n = 0; n < 8; ++n) {
                unsigned d0, d1, d2, d3;
                const unsigned addr = kbuf +
                    (unsigned)(((n*8 + (lane & 7)) * KSTRb + kcp*32 + (lane >> 3) * 8) * 2);
                ldsm_x4(d0, d1, d2, d3, addr);
                mma_bf16(sf[0][n], qa[0][2*kcp],     d0, d1);
                mma_bf16(sf[0][n], qa[0][2*kcp + 1], d2, d3);
                mma_bf16(sf[1][n], qa[1][2*kcp],     d0, d1);
                mma_bf16(sf[1][n], qa[1][2*kcp + 1], d2, d3);
            }
        }

        // ---- online softmax (log2 domain) + register-direct P frags ----
        unsigned pa[2][4][4];
        #pragma unroll
        for (int mq = 0; mq < 2; ++mq) {
            float mx0 = -1e30f, mx1 = -1e30f;
            #pragma unroll
            for (int n = 0; n < 8; ++n) {
                mx0 = fmaxf(mx0, fmaxf(sf[mq][n][0], sf[mq][n][1]));
                mx1 = fmaxf(mx1, fmaxf(sf[mq][n][2], sf[mq][n][3]));
            }
            mx0 = fmaxf(mx0, __shfl_xor_sync(0xffffffffu, mx0, 1));
            mx0 = fmaxf(mx0, __shfl_xor_sync(0xffffffffu, mx0, 2));
            mx1 = fmaxf(mx1, __shfl_xor_sync(0xffffffffu, mx1, 1));
            mx1 = fmaxf(mx1, __shfl_xor_sync(0xffffffffu, mx1, 2));

            const float mn0 = fmaxf(mM[mq][0], mx0);
            const float mn1 = fmaxf(mM[mq][1], mx1);
            const float al0 = ex2(mM[mq][0] - mn0);
            const float al1 = ex2(mM[mq][1] - mn1);

            float s0 = 0.f, s1 = 0.f;
            #pragma unroll
            for (int n = 0; n < 8; ++n) {
                sf[mq][n][0] = ex2(sf[mq][n][0] - mn0); s0 += sf[mq][n][0];
                sf[mq][n][1] = ex2(sf[mq][n][1] - mn0); s0 += sf[mq][n][1];
                sf[mq][n][2] = ex2(sf[mq][n][2] - mn1); s1 += sf[mq][n][2];
                sf[mq][n][3] = ex2(sf[mq][n][3] - mn1); s1 += sf[mq][n][3];
            }
            s0 += __shfl_xor_sync(0xffffffffu, s0, 1);
            s0 += __shfl_xor_sync(0xffffffffu, s0, 2);
            s1 += __shfl_xor_sync(0xffffffffu, s1, 1);
            s1 += __shfl_xor_sync(0xffffffffu, s1, 2);

            lL[mq][0] = lL[mq][0] * al0 + s0;  mM[mq][0] = mn0;
            lL[mq][1] = lL[mq][1] * al1 + s1;  mM[mq][1] = mn1;

            #pragma unroll
            for (int n = 0; n < 8; ++n) {
                of[mq][n][0] *= al0; of[mq][n][1] *= al0;
                of[mq][n][2] *= al1; of[mq][n][3] *= al1;
            }

            // P A-fragments directly from S C-fragments (layouts coincide):
            // chunk kc covers keys kc*16..+15 = S-tiles {2kc, 2kc+1}.
            #pragma unroll
            for (int kc = 0; kc < 4; ++kc) {
                pa[mq][kc][0] = pack_bf16(sf[mq][2*kc    ][0], sf[mq][2*kc    ][1]);
                pa[mq][kc][1] = pack_bf16(sf[mq][2*kc    ][2], sf[mq][2*kc    ][3]);
                pa[mq][kc][2] = pack_bf16(sf[mq][2*kc + 1][0], sf[mq][2*kc + 1][1]);
                pa[mq][kc][3] = pack_bf16(sf[mq][2*kc + 1][2], sf[mq][2*kc + 1][3]);
            }
        }

        // ---- PV: O(32x64) += P(32x64) V(64x64); each ldsm_t feeds 4 MMAs ----
        #pragma unroll
        for (int kc = 0; kc < 4; ++kc) {
            #pragma unroll
            for (int np = 0; np < 4; ++np) {
                unsigned d0, d1, d2, d3;
                const unsigned addr = vbuf + (unsigned)(
                    ((kc*16 + ((lane >> 3) & 1) * 8 + (lane & 7)) * KSTRb
                     + np*16 + (lane >> 4) * 8) * 2);
                ldsm_x4_t(d0, d1, d2, d3, addr);
                mma_bf16(of[0][2*np],     pa[0][kc], d0, d1);
                mma_bf16(of[0][2*np + 1], pa[0][kc], d2, d3);
                mma_bf16(of[1][2*np],     pa[1][kc], d0, d1);
                mma_bf16(of[1][2*np + 1], pa[1][kc], d2, d3);
            }
        }
        __syncthreads();
    }

    // ---- epilogue ----
    #pragma unroll
    for (int mq = 0; mq < 2; ++mq) {
        const float inv0 = 1.f / lL[mq][0];
        const float inv1 = 1.f / lL[mq][1];
        __half* ob = O + (size_t)(q0 + w*32 + mq*16 + grp) * DM + h * DH;
        #pragma unroll
        for (int n = 0; n < 8; ++n) {
            *(unsigned*)&ob[n*8 + 2*tig] =
                pack_f16(of[mq][n][0] * inv0, of[mq][n][1] * inv0);
            *(unsigned*)&ob[(size_t)8 * DM + n*8 + 2*tig] =
                pack_f16(of[mq][n][2] * inv1, of[mq][n][3] * inv1);
        }
    }
}

#define ATTN_SMEM (4 * BKV * KSTRb * 2)   // 36864 B

// ---------------------------------------------------------------------------
// out = LayerNorm(A + sum of NB fp16 partials of B) * gamma + beta.
// ---------------------------------------------------------------------------
template<int NB, bool DUAL>
__global__ void __launch_bounds__(128)
add_ln_kernel(const float* __restrict__ A, const __half* __restrict__ B,
              const float* __restrict__ gamma, const float* __restrict__ beta,
              float* __restrict__ O, __half* __restrict__ Oh)
{
    __shared__ float red[4];
    const int row = blockIdx.x;
    const int t   = threadIdx.x;
    const int wid = t >> 5;
    const int lane = t & 31;

    const size_t base = (size_t)row * DM + t * 4;
    float4 v = *(const float4*)(A + base);
    #pragma unroll
    for (int p = 0; p < NB; ++p) {
        uint2 bu = *(const uint2*)(B + (size_t)p * S_LEN * DM + base);
        float2 b0 = unpack_f16(bu.x);
        float2 b1 = unpack_f16(bu.y);
        v.x += b0.x; v.y += b0.y; v.z += b1.x; v.w += b1.y;
    }

    float s = v.x + v.y + v.z + v.w;
    #pragma unroll
    for (int o = 16; o > 0; o >>= 1) s += __shfl_xor_sync(0xffffffffu, s, o);
    if (lane == 0) red[wid] = s;
    __syncthreads();
    const float mu = (red[0] + red[1] + red[2] + red[3]) * (1.f / DM);

    float4 d = make_float4(v.x - mu, v.y - mu, v.z - mu, v.w - mu);
    float ss = d.x*d.x + d.y*d.y + d.z*d.z + d.w*d.w;
    #pragma unroll
    for (int o = 16; o > 0; o >>= 1) ss += __shfl_xor_sync(0xffffffffu, ss, o);
    __syncthreads();
    if (lane == 0) red[wid] = ss;
    __syncthreads();
    const float var  = (red[0] + red[1] + red[2] + red[3]) * (1.f / DM);
    const float rstd = rsqrtf(var + 1e-6f);

    float4 g  = *(const float4*)(gamma + t * 4);
    float4 be = *(const float4*)(beta  + t * 4);
    float4 o;
    o.x = d.x * rstd * g.x + be.x;
    o.y = d.y * rstd * g.y + be.y;
    o.z = d.z * rstd * g.z + be.z;
    o.w = d.w * rstd * g.w + be.w;
    *(float4*)(O + base) = o;
    if (DUAL) {
        unsigned lo = pack_f16(o.x, o.y);
        unsigned hi = pack_f16(o.z, o.w);
        *(uint2*)(Oh + base) = make_uint2(lo, hi);
    }
}

// ---------------------------------------------------------------------------
// kernel_launch
// ---------------------------------------------------------------------------
extern "C" void kernel_launch(void* const* d_in, const int* in_sizes, int n_in,
                              void* d_out, int out_size)
{
    const float* x       = (const float*)d_in[0];
    const float* wq_w    = (const float*)d_in[1];
    const float* wq_b    = (const float*)d_in[2];
    const float* wk_w    = (const float*)d_in[3];
    const float* wk_b    = (const float*)d_in[4];
    const float* wv_w    = (const float*)d_in[5];
    const float* wv_b    = (const float*)d_in[6];
    const float* dense_w = (const float*)d_in[7];
    const float* dense_b = (const float*)d_in[8];
    const float* l1_w    = (const float*)d_in[9];
    const float* l1_b    = (const float*)d_in[10];
    const float* l2_w    = (const float*)d_in[11];
    const float* l2_b    = (const float*)d_in[12];
    const float* ln1_g   = (const float*)d_in[13];
    const float* ln1_b   = (const float*)d_in[14];
    const float* ln2_g   = (const float*)d_in[15];
    const float* ln2_b   = (const float*)d_in[16];
    float* out = (float*)d_out;

    __half *xh, *wqh, *wkh, *wvh, *dwh, *l1h, *l2h, *CTXh, *O1h, *Hh, *ATT, *F;
    __nv_bfloat16 *Qb, *Kb, *Vb;
    float *O1;
    cudaGetSymbolAddress((void**)&xh,   g_xh);
    cudaGetSymbolAddress((void**)&wqh,  g_wqh);
    cudaGetSymbolAddress((void**)&wkh,  g_wkh);
    cudaGetSymbolAddress((void**)&wvh,  g_wvh);
    cudaGetSymbolAddress((void**)&dwh,  g_dwh);
    cudaGetSymbolAddress((void**)&l1h,  g_l1h);
    cudaGetSymbolAddress((void**)&l2h,  g_l2h);
    cudaGetSymbolAddress((void**)&Qb,   g_Qb);
    cudaGetSymbolAddress((void**)&Kb,   g_Kb);
    cudaGetSymbolAddress((void**)&Vb,   g_Vb);
    cudaGetSymbolAddress((void**)&CTXh, g_CTXh);
    cudaGetSymbolAddress((void**)&O1h,  g_O1h);
    cudaGetSymbolAddress((void**)&Hh,   g_Hh);
    cudaGetSymbolAddress((void**)&ATT,  g_ATT);
    cudaGetSymbolAddress((void**)&O1,   g_O1);
    cudaGetSymbolAddress((void**)&F,    g_F);

    cudaFuncSetAttribute(flash_attn_bf16_kernel,
                         cudaFuncAttributeMaxDynamicSharedMemorySize, ATTN_SMEM);

    // fp32 -> fp16 conversions, single merged launch
    f2h_all_kernel<<<5120, 256>>>(x, xh, wq_w, wqh, wk_w, wkh, wv_w, wvh,
                                  dense_w, dwh, l1_w, l1h, l2_w, l2h);

    // QKV projections, batched. Q scale = (1/sqrt(64)) * log2(e) for exp2 softmax.
    gemm_f16_kernel<false, 1, 1><<<dim3(DM/128, S_LEN/128, 3), 256>>>(
        xh,
        wqh, wq_b, Qb,
        wkh, wk_b, Kb,
        wvh, wv_b, Vb,
        DM, DM, 0.125f * 1.44269504088896f, 1.f, 1.f);

    // attention (BQ=128: 256 CTAs; fp16 CTX out)
    flash_attn_bf16_kernel<<<dim3(S_LEN / BQ, NH), 128, ATTN_SMEM>>>(
        Qb, Kb, Vb, CTXh);

    // dense proj: split-K=2, fp16 partials + fused-reduce LN
    gemm_f16_kernel<false, 0, 2><<<dim3(DM/128, S_LEN/128, 2), 256>>>(
        CTXh,
        dwh, dense_b, ATT,
        dwh, dense_b, ATT,
        dwh, dense_b, ATT,
        DM, DM, 1.f, 1.f, 1.f);
    add_ln_kernel<2, true><<<S_LEN, 128>>>(x, ATT, ln1_g, ln1_b, O1, O1h);

    // FFN1 (grid 512, H fp16)
    gemm_f16_kernel<true, 2, 1><<<dim3(DFF_/128, S_LEN/128, 1), 256>>>(
        O1h,
        l1h, l1_b, Hh,
        l1h, l1_b, Hh,
        l1h, l1_b, Hh,
        DFF_, DM, 1.f, 1.f, 1.f);

    // FFN2: split-K=4, fp16 partials + fused-reduce LN
    gemm_f16_kernel<false, 0, 4><<<dim3(DM/128, S_LEN/128, 4), 256>>>(
        Hh,
        l2h, l2_b, F,
        l2h, l2_b, F,
        l2h, l2_b, F,
        DM, DFF_, 1.f, 1.f, 1.f);
    add_ln_kernel<4, false><<<S_LEN, 128>>>(O1, F, ln2_g, ln2_b, out, (__half*)0);
}